// round 2
// baseline (speedup 1.0000x reference)
#include <cuda_runtime.h>
#include <cstdint>
#include <math.h>

#define U 256
#define INWID 128
#define BATCH 128
#define TLEN 1024
#define OUTD 400

// d_out layout: output [B*400] | d_t [B*256] | gru1_h [B*256] | gru2_h [B*256]
#define OUT_OFF 0
#define DT_OFF  (BATCH*OUTD)              // 51200
#define G1_OFF  (DT_OFF + BATCH*U)        // 83968
#define G2_OFF  (G1_OFF + BATCH*U)        // 116736

// -------- scratch (no allocations allowed) --------
__device__ __align__(16) float g_W1t[U * U];
__device__ __align__(16) float g_dt[BATCH * U];
__device__ __align__(16) float g_query[BATCH * U];
__device__ __align__(16) float g_scores[BATCH * TLEN];
__device__ __align__(16) float g_gru1in[BATCH * U];

__device__ __forceinline__ float sigmoidf_(float x) {
    return 1.0f / (1.0f + __expf(-x));
}

__device__ __forceinline__ uint32_t f32_to_tf32(float x) {
    uint32_t r;
    asm("cvt.rna.tf32.f32 %0, %1;" : "=r"(r) : "f"(x));
    return r;
}

__device__ __forceinline__ void mma_tf32(float c[4], const uint32_t a[4], const uint32_t b[2]) {
    asm volatile(
        "mma.sync.aligned.m16n8k8.row.col.f32.tf32.tf32.f32 "
        "{%0,%1,%2,%3}, {%4,%5,%6,%7}, {%8,%9}, {%0,%1,%2,%3};\n"
        : "+f"(c[0]), "+f"(c[1]), "+f"(c[2]), "+f"(c[3])
        : "r"(a[0]), "r"(a[1]), "r"(a[2]), "r"(a[3]), "r"(b[0]), "r"(b[1]));
}

// ================= K0: W1 [j][k] -> W1t [k][j] =================
__global__ void k_transpose(const float* __restrict__ W1) {
    __shared__ float tile[32][33];
    int k0 = blockIdx.x * 32, j0 = blockIdx.y * 32;
    int tx = threadIdx.x, ty = threadIdx.y;  // 32 x 8
#pragma unroll
    for (int r = 0; r < 32; r += 8)
        tile[ty + r][tx] = W1[(j0 + ty + r) * U + k0 + tx];
    __syncthreads();
#pragma unroll
    for (int r = 0; r < 32; r += 8)
        g_W1t[(k0 + ty + r) * U + j0 + tx] = tile[tx][ty + r];
}

// ================= K1: attention GRU cell + query projection =================
__global__ void k_attn_gru(const float* __restrict__ x, const float* __restrict__ h0,
                           const float* __restrict__ Wih, const float* __restrict__ Whh,
                           const float* __restrict__ bih, const float* __restrict__ bhh,
                           const float* __restrict__ W2, float* __restrict__ dt_out) {
    int b = blockIdx.x, j = threadIdx.x;  // 256 threads
    __shared__ float sx[INWID], sh[U], sd[U];
    if (j < INWID) sx[j] = x[b * INWID + j];
    sh[j] = h0[b * U + j];
    __syncthreads();

    float gr = bih[j], gz = bih[U + j], gn = bih[2 * U + j];
    const float* wr = Wih + j * INWID;
    const float* wz = Wih + (U + j) * INWID;
    const float* wn = Wih + (2 * U + j) * INWID;
#pragma unroll 4
    for (int k = 0; k < INWID; k++) {
        float xv = sx[k];
        gr += xv * wr[k]; gz += xv * wz[k]; gn += xv * wn[k];
    }
    float hr = bhh[j], hz = bhh[U + j], hn = bhh[2 * U + j];
    const float* vr = Whh + j * U;
    const float* vz = Whh + (U + j) * U;
    const float* vn = Whh + (2 * U + j) * U;
#pragma unroll 4
    for (int k = 0; k < U; k++) {
        float hv = sh[k];
        hr += hv * vr[k]; hz += hv * vz[k]; hn += hv * vn[k];
    }
    float r = sigmoidf_(gr + hr);
    float z = sigmoidf_(gz + hz);
    float n = tanhf(gn + r * hn);
    float d = (1.0f - z) * n + z * sh[j];
    sd[j] = d;
    g_dt[b * U + j] = d;
    dt_out[b * U + j] = d;
    __syncthreads();

    float q = 0.f;
    const float* w2r = W2 + j * U;
#pragma unroll 4
    for (int k = 0; k < U; k++) q += sd[k] * w2r[k];
    g_query[b * U + j] = q;
}

// ================= K2: scores = v . tanh(memory@W1^T + query)  (TF32 mma) ====
// Block tile: 64 t-rows x 256 key-dims, K = 256. Grid (B, T/64). 8 warps.
__global__ void __launch_bounds__(256, 2)
k_scores(const float* __restrict__ memory, const float* __restrict__ v) {
    int b = blockIdx.x;
    int t0 = blockIdx.y * 64;
    int tid = threadIdx.x;
    int lane = tid & 31, w = tid >> 5;

    __shared__ float As[64][36];    // 64 t x 32 k (pad 36: conflict-free frag loads)
    __shared__ float Bs[32][264];   // 32 k x 256 j (pad 264)
    __shared__ float sq[U], sv[U];
    __shared__ float spart[64][8];

    sq[tid] = g_query[b * U + tid];
    sv[tid] = v[tid];

    float acc[4][4][4];
#pragma unroll
    for (int mt = 0; mt < 4; mt++)
#pragma unroll
        for (int nt = 0; nt < 4; nt++)
#pragma unroll
            for (int i = 0; i < 4; i++) acc[mt][nt][i] = 0.0f;

    const float* Abase = memory + ((size_t)b * TLEN + t0) * U;

    for (int k0 = 0; k0 < U; k0 += 32) {
        // ---- stage A: 64x32 floats (2 float4 per thread) ----
#pragma unroll
        for (int i = 0; i < 2; i++) {
            int f4 = tid + 256 * i;
            int row = f4 >> 3, c4 = (f4 & 7) * 4;
            float4 val = *(const float4*)(Abase + row * U + k0 + c4);
            As[row][c4 + 0] = __uint_as_float(f32_to_tf32(val.x));
            As[row][c4 + 1] = __uint_as_float(f32_to_tf32(val.y));
            As[row][c4 + 2] = __uint_as_float(f32_to_tf32(val.z));
            As[row][c4 + 3] = __uint_as_float(f32_to_tf32(val.w));
        }
        // ---- stage B: 32x256 floats (8 float4 per thread) ----
#pragma unroll
        for (int i = 0; i < 8; i++) {
            int f4 = tid + 256 * i;
            int row = f4 >> 6, c4 = (f4 & 63) * 4;
            float4 val = *(const float4*)(g_W1t + (size_t)(k0 + row) * U + c4);
            Bs[row][c4 + 0] = __uint_as_float(f32_to_tf32(val.x));
            Bs[row][c4 + 1] = __uint_as_float(f32_to_tf32(val.y));
            Bs[row][c4 + 2] = __uint_as_float(f32_to_tf32(val.z));
            Bs[row][c4 + 3] = __uint_as_float(f32_to_tf32(val.w));
        }
        __syncthreads();

        int r0 = lane >> 2, cA = lane & 3;
        int rB = lane & 3, cB = lane >> 2;
#pragma unroll
        for (int kk = 0; kk < 32; kk += 8) {
            uint32_t a[4][4];
#pragma unroll
            for (int mt = 0; mt < 4; mt++) {
                a[mt][0] = __float_as_uint(As[mt * 16 + r0][kk + cA]);
                a[mt][1] = __float_as_uint(As[mt * 16 + r0 + 8][kk + cA]);
                a[mt][2] = __float_as_uint(As[mt * 16 + r0][kk + cA + 4]);
                a[mt][3] = __float_as_uint(As[mt * 16 + r0 + 8][kk + cA + 4]);
            }
            uint32_t bb[4][2];
#pragma unroll
            for (int nt = 0; nt < 4; nt++) {
                int j = w * 32 + nt * 8 + cB;
                bb[nt][0] = __float_as_uint(Bs[kk + rB][j]);
                bb[nt][1] = __float_as_uint(Bs[kk + rB + 4][j]);
            }
#pragma unroll
            for (int mt = 0; mt < 4; mt++)
#pragma unroll
                for (int nt = 0; nt < 4; nt++)
                    mma_tf32(acc[mt][nt], a[mt], bb[nt]);
        }
        __syncthreads();
    }

    // ---- epilogue: v . tanh(key + query), reduce 256 key dims -> score ----
    float part[8];
#pragma unroll
    for (int i = 0; i < 8; i++) part[i] = 0.0f;
    int r0 = lane >> 2, q4 = lane & 3;
#pragma unroll
    for (int mt = 0; mt < 4; mt++) {
#pragma unroll
        for (int nt = 0; nt < 4; nt++) {
            int j0 = w * 32 + nt * 8 + 2 * q4;
            float q0 = sq[j0], q1 = sq[j0 + 1];
            float v0 = sv[j0], v1 = sv[j0 + 1];
            part[mt * 2 + 0] += v0 * tanhf(acc[mt][nt][0] + q0) + v1 * tanhf(acc[mt][nt][1] + q1);
            part[mt * 2 + 1] += v0 * tanhf(acc[mt][nt][2] + q0) + v1 * tanhf(acc[mt][nt][3] + q1);
        }
    }
    // reduce across the 4 lanes that share a row (lane%4 dimension)
#pragma unroll
    for (int i = 0; i < 8; i++) {
        part[i] += __shfl_xor_sync(0xffffffffu, part[i], 1);
        part[i] += __shfl_xor_sync(0xffffffffu, part[i], 2);
    }
    if ((lane & 3) == 0) {
#pragma unroll
        for (int mt = 0; mt < 4; mt++) {
            spart[mt * 16 + r0][w] = part[mt * 2 + 0];
            spart[mt * 16 + r0 + 8][w] = part[mt * 2 + 1];
        }
    }
    __syncthreads();
    if (tid < 64) {
        float s = 0.0f;
#pragma unroll
        for (int i = 0; i < 8; i++) s += spart[tid][i];
        g_scores[b * TLEN + t0 + tid] = s;
    }
}

// ================= K3: softmax(T) + context + proj =================
__global__ void k_softmax_ctx(const float* __restrict__ memory,
                              const float* __restrict__ projW,
                              const float* __restrict__ projb) {
    int b = blockIdx.x;
    int tid = threadIdx.x;  // 1024 threads
    int lane = tid & 31, warp = tid >> 5;

    __shared__ float sw[TLEN];
    __shared__ float redmax[32], redsum[32];
    __shared__ float spart[4][U];
    __shared__ float sctx[U], sdt[U];

    float s = g_scores[b * TLEN + tid];
    float m = s;
#pragma unroll
    for (int off = 16; off; off >>= 1) m = fmaxf(m, __shfl_xor_sync(0xffffffffu, m, off));
    if (lane == 0) redmax[warp] = m;
    __syncthreads();
    if (tid == 0) {
        float mm = redmax[0];
#pragma unroll
        for (int i = 1; i < 32; i++) mm = fmaxf(mm, redmax[i]);
        redmax[0] = mm;
    }
    __syncthreads();
    float mx = redmax[0];
    float e = __expf(s - mx);
    sw[tid] = e;
    float t = e;
#pragma unroll
    for (int off = 16; off; off >>= 1) t += __shfl_xor_sync(0xffffffffu, t, off);
    if (lane == 0) redsum[warp] = t;
    __syncthreads();
    if (tid == 0) {
        float ss = 0.0f;
#pragma unroll
        for (int i = 0; i < 32; i++) ss += redsum[i];
        redsum[0] = ss;
    }
    __syncthreads();
    float inv = 1.0f / redsum[0];

    // context: thread (u = tid&255, tq = tid>>8) handles a quarter of T
    int u = tid & 255, tq = tid >> 8;
    const float* mp = memory + ((size_t)b * TLEN + tq * 256) * U + u;
    const float* wp = sw + tq * 256;
    float c = 0.0f;
#pragma unroll 8
    for (int tt = 0; tt < 256; tt++) c += wp[tt] * mp[(size_t)tt * U];
    spart[tq][u] = c * inv;
    __syncthreads();

    if (tid < U) {
        float ctx = spart[0][tid] + spart[1][tid] + spart[2][tid] + spart[3][tid];
        sctx[tid] = ctx;
        sdt[tid] = g_dt[b * U + tid];
    }
    __syncthreads();

    if (tid < U) {
        int j = tid;
        float acc = projb[j];
        const float* wrow = projW + (size_t)j * 2 * U;
#pragma unroll 4
        for (int k = 0; k < U; k++) acc += sdt[k] * wrow[k];
#pragma unroll 4
        for (int k = 0; k < U; k++) acc += sctx[k] * wrow[U + k];
        g_gru1in[b * U + j] = acc;
    }
}

// ================= K4: GRU1 + GRU2 + output head =================
__global__ void k_tail(const float* __restrict__ h1_0, const float* __restrict__ h2_0,
                       const float* __restrict__ g1Wih, const float* __restrict__ g1Whh,
                       const float* __restrict__ g1bih, const float* __restrict__ g1bhh,
                       const float* __restrict__ g2Wih, const float* __restrict__ g2Whh,
                       const float* __restrict__ g2bih, const float* __restrict__ g2bhh,
                       const float* __restrict__ outW, const float* __restrict__ outb,
                       float* __restrict__ d_out) {
    int b = blockIdx.x, j = threadIdx.x;  // 256 threads
    __shared__ float sin1[U], sh1[U], sin2[U], sh2[U], sbf[U];
    sin1[j] = g_gru1in[b * U + j];
    sh1[j] = h1_0[b * U + j];
    sh2[j] = h2_0[b * U + j];
    __syncthreads();

    // GRU1
    {
        float gr = g1bih[j], gz = g1bih[U + j], gn = g1bih[2 * U + j];
        const float* wr = g1Wih + j * U;
        const float* wz = g1Wih + (U + j) * U;
        const float* wn = g1Wih + (2 * U + j) * U;
        float hr = g1bhh[j], hz = g1bhh[U + j], hn = g1bhh[2 * U + j];
        const float* vr = g1Whh + j * U;
        const float* vz = g1Whh + (U + j) * U;
        const float* vn = g1Whh + (2 * U + j) * U;
#pragma unroll 4
        for (int k = 0; k < U; k++) {
            float xv = sin1[k], hv = sh1[k];
            gr += xv * wr[k]; gz += xv * wz[k]; gn += xv * wn[k];
            hr += hv * vr[k]; hz += hv * vz[k]; hn += hv * vn[k];
        }
        float r = sigmoidf_(gr + hr);
        float z = sigmoidf_(gz + hz);
        float n = tanhf(gn + r * hn);
        float h1 = (1.0f - z) * n + z * sh1[j];
        d_out[G1_OFF + b * U + j] = h1;
        sin2[j] = sin1[j] + h1;
    }
    __syncthreads();

    // GRU2
    {
        float gr = g2bih[j], gz = g2bih[U + j], gn = g2bih[2 * U + j];
        const float* wr = g2Wih + j * U;
        const float* wz = g2Wih + (U + j) * U;
        const float* wn = g2Wih + (2 * U + j) * U;
        float hr = g2bhh[j], hz = g2bhh[U + j], hn = g2bhh[2 * U + j];
        const float* vr = g2Whh + j * U;
        const float* vz = g2Whh + (U + j) * U;
        const float* vn = g2Whh + (2 * U + j) * U;
#pragma unroll 4
        for (int k = 0; k < U; k++) {
            float xv = sin2[k], hv = sh2[k];
            gr += xv * wr[k]; gz += xv * wz[k]; gn += xv * wn[k];
            hr += hv * vr[k]; hz += hv * vz[k]; hn += hv * vn[k];
        }
        float r = sigmoidf_(gr + hr);
        float z = sigmoidf_(gz + hz);
        float n = tanhf(gn + r * hn);
        float h2 = (1.0f - z) * n + z * sh2[j];
        d_out[G2_OFF + b * U + j] = h2;
        sbf[j] = sin2[j] + h2;
    }
    __syncthreads();

    // output head: 400 rows
    for (int o = j; o < OUTD; o += 256) {
        float acc = outb[o];
        const float* wrow = outW + (size_t)o * U;
#pragma unroll 4
        for (int k = 0; k < U; k++) acc += sbf[k] * wrow[k];
        d_out[OUT_OFF + b * OUTD + o] = acc;
    }
}

// ================= launch =================
extern "C" void kernel_launch(void* const* d_in, const int* in_sizes, int n_in,
                              void* d_out, int out_size) {
    const float* dec   = (const float*)d_in[0];
    const float* mem   = (const float*)d_in[1];
    const float* ah    = (const float*)d_in[2];
    const float* h1    = (const float*)d_in[3];
    const float* h2    = (const float*)d_in[4];
    const float* W1    = (const float*)d_in[5];
    const float* W2    = (const float*)d_in[6];
    const float* v     = (const float*)d_in[7];
    const float* aWih  = (const float*)d_in[8];
    const float* aWhh  = (const float*)d_in[9];
    const float* abih  = (const float*)d_in[10];
    const float* abhh  = (const float*)d_in[11];
    const float* g1Wih = (const float*)d_in[12];
    const float* g1Whh = (const float*)d_in[13];
    const float* g1bih = (const float*)d_in[14];
    const float* g1bhh = (const float*)d_in[15];
    const float* g2Wih = (const float*)d_in[16];
    const float* g2Whh = (const float*)d_in[17];
    const float* g2bih = (const float*)d_in[18];
    const float* g2bhh = (const float*)d_in[19];
    const float* projW = (const float*)d_in[20];
    const float* projb = (const float*)d_in[21];
    const float* outW  = (const float*)d_in[22];
    const float* outb  = (const float*)d_in[23];
    float* out = (float*)d_out;

    k_transpose<<<dim3(8, 8), dim3(32, 8)>>>(W1);
    k_attn_gru<<<BATCH, 256>>>(dec, ah, aWih, aWhh, abih, abhh, W2, out + DT_OFF);
    k_scores<<<dim3(BATCH, TLEN / 64), 256>>>(mem, v);
    k_softmax_ctx<<<BATCH, 1024>>>(mem, projW, projb);
    k_tail<<<BATCH, 256>>>(h1, h2, g1Wih, g1Whh, g1bih, g1bhh,
                           g2Wih, g2Whh, g2bih, g2bhh, outW, outb, out);
}

// round 5
// speedup vs baseline: 1.0244x; 1.0244x over previous
#include <cuda_runtime.h>
#include <cstdint>
#include <math.h>

#define U 256
#define INWID 128
#define BATCH 128
#define TLEN 1024
#define OUTD 400

// d_out layout: output [B*400] | d_t [B*256] | gru1_h [B*256] | gru2_h [B*256]
#define OUT_OFF 0
#define DT_OFF  (BATCH*OUTD)
#define G1_OFF  (DT_OFF + BATCH*U)
#define G2_OFF  (G1_OFF + BATCH*U)

// -------- scratch (no allocations allowed) --------
__device__ __align__(16) float g_W1t[U * U];
__device__ __align__(16) float g_dt[BATCH * U];
__device__ __align__(16) float g_query[BATCH * U];
__device__ __align__(16) float g_scores[BATCH * TLEN];      // scores, then normalized weights
__device__ __align__(16) float g_ctxpart[BATCH * 4 * U];

__device__ __forceinline__ float sigmoidf_(float x) {
    return 1.0f / (1.0f + __expf(-x));
}

__device__ __forceinline__ float tanh_fast(float x) {
    float y;
    asm("tanh.approx.f32 %0, %1;" : "=f"(y) : "f"(x));
    return y;
}

__device__ __forceinline__ uint32_t f32_to_tf32(float x) {
    uint32_t r;
    asm("cvt.rna.tf32.f32 %0, %1;" : "=r"(r) : "f"(x));
    return r;
}

__device__ __forceinline__ void mma_tf32(float c[4], const uint32_t a[4], const uint32_t b[2]) {
    asm volatile(
        "mma.sync.aligned.m16n8k8.row.col.f32.tf32.tf32.f32 "
        "{%0,%1,%2,%3}, {%4,%5,%6,%7}, {%8,%9}, {%0,%1,%2,%3};\n"
        : "+f"(c[0]), "+f"(c[1]), "+f"(c[2]), "+f"(c[3])
        : "r"(a[0]), "r"(a[1]), "r"(a[2]), "r"(a[3]), "r"(b[0]), "r"(b[1]));
}

// ================= K0: W1 [j][k] -> W1t [k][j] =================
__global__ void k_transpose(const float* __restrict__ W1) {
    __shared__ float tile[32][33];
    int k0 = blockIdx.x * 32, j0 = blockIdx.y * 32;
    int tx = threadIdx.x, ty = threadIdx.y;  // 32 x 8
#pragma unroll
    for (int r = 0; r < 32; r += 8)
        tile[ty + r][tx] = W1[(j0 + ty + r) * U + k0 + tx];
    __syncthreads();
#pragma unroll
    for (int r = 0; r < 32; r += 8)
        g_W1t[(k0 + ty + r) * U + j0 + tx] = tile[tx][ty + r];
}

// ================= K1: attention GRU cell + query projection =================
__global__ void k_attn_gru(const float* __restrict__ x, const float* __restrict__ h0,
                           const float* __restrict__ Wih, const float* __restrict__ Whh,
                           const float* __restrict__ bih, const float* __restrict__ bhh,
                           const float* __restrict__ W2, float* __restrict__ dt_out) {
    int b = blockIdx.x, j = threadIdx.x;  // 256 threads
    __shared__ float sx[INWID], sh[U], sd[U];
    if (j < INWID) sx[j] = x[b * INWID + j];
    sh[j] = h0[b * U + j];
    __syncthreads();

    float gr = bih[j], gz = bih[U + j], gn = bih[2 * U + j];
    const float* wr = Wih + j * INWID;
    const float* wz = Wih + (U + j) * INWID;
    const float* wn = Wih + (2 * U + j) * INWID;
#pragma unroll 4
    for (int k = 0; k < INWID; k++) {
        float xv = sx[k];
        gr += xv * wr[k]; gz += xv * wz[k]; gn += xv * wn[k];
    }
    float hr = bhh[j], hz = bhh[U + j], hn = bhh[2 * U + j];
    const float* vr = Whh + j * U;
    const float* vz = Whh + (U + j) * U;
    const float* vn = Whh + (2 * U + j) * U;
#pragma unroll 4
    for (int k = 0; k < U; k++) {
        float hv = sh[k];
        hr += hv * vr[k]; hz += hv * vz[k]; hn += hv * vn[k];
    }
    float r = sigmoidf_(gr + hr);
    float z = sigmoidf_(gz + hz);
    float n = tanhf(gn + r * hn);
    float d = (1.0f - z) * n + z * sh[j];
    sd[j] = d;
    g_dt[b * U + j] = d;
    dt_out[b * U + j] = d;
    __syncthreads();

    float q = 0.f;
    const float* w2r = W2 + j * U;
#pragma unroll 4
    for (int k = 0; k < U; k++) q += sd[k] * w2r[k];
    g_query[b * U + j] = q;
}

// ================= K2: scores = v . tanh(memory@W1^T + query)  (TF32 mma) ====
// Block tile: 64 t-rows x 256 key-dims, K = 256. Grid (B, T/64). 8 warps.
__global__ void __launch_bounds__(256, 2)
k_scores(const float* __restrict__ memory, const float* __restrict__ v) {
    int b = blockIdx.x;
    int t0 = blockIdx.y * 64;
    int tid = threadIdx.x;
    int lane = tid & 31, w = tid >> 5;

    __shared__ float As[64][36];    // 64 t x 32 k
    __shared__ float Bs[32][264];   // 32 k x 256 j
    __shared__ float sq[U], sv[U];
    __shared__ float spart[64][8];

    sq[tid] = g_query[b * U + tid];
    sv[tid] = v[tid];

    float acc[4][4][4];
#pragma unroll
    for (int mt = 0; mt < 4; mt++)
#pragma unroll
        for (int nt = 0; nt < 4; nt++)
#pragma unroll
            for (int i = 0; i < 4; i++) acc[mt][nt][i] = 0.0f;

    const float* Abase = memory + ((size_t)b * TLEN + t0) * U;

    for (int k0 = 0; k0 < U; k0 += 32) {
#pragma unroll
        for (int i = 0; i < 2; i++) {
            int f4 = tid + 256 * i;
            int row = f4 >> 3, c4 = (f4 & 7) * 4;
            float4 val = *(const float4*)(Abase + row * U + k0 + c4);
            As[row][c4 + 0] = __uint_as_float(f32_to_tf32(val.x));
            As[row][c4 + 1] = __uint_as_float(f32_to_tf32(val.y));
            As[row][c4 + 2] = __uint_as_float(f32_to_tf32(val.z));
            As[row][c4 + 3] = __uint_as_float(f32_to_tf32(val.w));
        }
#pragma unroll
        for (int i = 0; i < 8; i++) {
            int f4 = tid + 256 * i;
            int row = f4 >> 6, c4 = (f4 & 63) * 4;
            float4 val = *(const float4*)(g_W1t + (size_t)(k0 + row) * U + c4);
            Bs[row][c4 + 0] = __uint_as_float(f32_to_tf32(val.x));
            Bs[row][c4 + 1] = __uint_as_float(f32_to_tf32(val.y));
            Bs[row][c4 + 2] = __uint_as_float(f32_to_tf32(val.z));
            Bs[row][c4 + 3] = __uint_as_float(f32_to_tf32(val.w));
        }
        __syncthreads();

        int r0 = lane >> 2, cA = lane & 3;
        int rB = lane & 3, cB = lane >> 2;
#pragma unroll
        for (int kk = 0; kk < 32; kk += 8) {
            uint32_t a[4][4];
#pragma unroll
            for (int mt = 0; mt < 4; mt++) {
                a[mt][0] = __float_as_uint(As[mt * 16 + r0][kk + cA]);
                a[mt][1] = __float_as_uint(As[mt * 16 + r0 + 8][kk + cA]);
                a[mt][2] = __float_as_uint(As[mt * 16 + r0][kk + cA + 4]);
                a[mt][3] = __float_as_uint(As[mt * 16 + r0 + 8][kk + cA + 4]);
            }
            uint32_t bb[4][2];
#pragma unroll
            for (int nt = 0; nt < 4; nt++) {
                int j = w * 32 + nt * 8 + cB;
                bb[nt][0] = __float_as_uint(Bs[kk + rB][j]);
                bb[nt][1] = __float_as_uint(Bs[kk + rB + 4][j]);
            }
#pragma unroll
            for (int mt = 0; mt < 4; mt++)
#pragma unroll
                for (int nt = 0; nt < 4; nt++)
                    mma_tf32(acc[mt][nt], a[mt], bb[nt]);
        }
        __syncthreads();
    }

    // ---- epilogue: v . tanh(key + query), MUFU.TANH ----
    float part[8];
#pragma unroll
    for (int i = 0; i < 8; i++) part[i] = 0.0f;
    int r0 = lane >> 2, q4 = lane & 3;
#pragma unroll
    for (int mt = 0; mt < 4; mt++) {
#pragma unroll
        for (int nt = 0; nt < 4; nt++) {
            int j0 = w * 32 + nt * 8 + 2 * q4;
            float q0 = sq[j0], q1 = sq[j0 + 1];
            float v0 = sv[j0], v1 = sv[j0 + 1];
            part[mt * 2 + 0] += v0 * tanh_fast(acc[mt][nt][0] + q0) + v1 * tanh_fast(acc[mt][nt][1] + q1);
            part[mt * 2 + 1] += v0 * tanh_fast(acc[mt][nt][2] + q0) + v1 * tanh_fast(acc[mt][nt][3] + q1);
        }
    }
#pragma unroll
    for (int i = 0; i < 8; i++) {
        part[i] += __shfl_xor_sync(0xffffffffu, part[i], 1);
        part[i] += __shfl_xor_sync(0xffffffffu, part[i], 2);
    }
    if ((lane & 3) == 0) {
#pragma unroll
        for (int mt = 0; mt < 4; mt++) {
            spart[mt * 16 + r0][w] = part[mt * 2 + 0];
            spart[mt * 16 + r0 + 8][w] = part[mt * 2 + 1];
        }
    }
    __syncthreads();
    if (tid < 64) {
        float s = 0.0f;
#pragma unroll
        for (int i = 0; i < 8; i++) s += spart[tid][i];
        g_scores[b * TLEN + t0 + tid] = s;
    }
}

// ================= K3a: softmax stats; normalize weights in-place ==========
__global__ void k_softmax_stats() {
    int b = blockIdx.x;
    int tid = threadIdx.x;  // 256 threads, 4 scores each
    int lane = tid & 31, warp = tid >> 5;
    __shared__ float red[8];

    float4 s = *(const float4*)(g_scores + b * TLEN + tid * 4);
    float m = fmaxf(fmaxf(s.x, s.y), fmaxf(s.z, s.w));
#pragma unroll
    for (int off = 16; off; off >>= 1) m = fmaxf(m, __shfl_xor_sync(0xffffffffu, m, off));
    if (lane == 0) red[warp] = m;
    __syncthreads();
    if (tid == 0) {
        float mm = red[0];
#pragma unroll
        for (int i = 1; i < 8; i++) mm = fmaxf(mm, red[i]);
        red[0] = mm;
    }
    __syncthreads();
    float mx = red[0];
    __syncthreads();

    float4 e;
    e.x = __expf(s.x - mx); e.y = __expf(s.y - mx);
    e.z = __expf(s.z - mx); e.w = __expf(s.w - mx);
    float t = e.x + e.y + e.z + e.w;
#pragma unroll
    for (int off = 16; off; off >>= 1) t += __shfl_xor_sync(0xffffffffu, t, off);
    if (lane == 0) red[warp] = t;
    __syncthreads();
    if (tid == 0) {
        float ss = 0.0f;
#pragma unroll
        for (int i = 0; i < 8; i++) ss += red[i];
        red[0] = 1.0f / ss;
    }
    __syncthreads();
    float inv = red[0];
    e.x *= inv; e.y *= inv; e.z *= inv; e.w *= inv;
    *(float4*)(g_scores + b * TLEN + tid * 4) = e;
}

// ================= K3b: context partials (grid B x 4) =================
__global__ void __launch_bounds__(256, 4)
k_context(const float* __restrict__ memory) {
    int b = blockIdx.x, ch = blockIdx.y;   // t range [ch*256, ch*256+256)
    int tid = threadIdx.x;
    int u4 = tid & 63;                     // float4 index over U
    int tg = tid >> 6;                     // 0..3, each handles 64 t's

    __shared__ float sw[256];
    __shared__ float4 part[4][64];

    sw[tid] = g_scores[b * TLEN + ch * 256 + tid];
    __syncthreads();

    const float* mp = memory + ((size_t)b * TLEN + ch * 256 + tg * 64) * U + u4 * 4;
    const float* wp = sw + tg * 64;
    float4 c = make_float4(0.f, 0.f, 0.f, 0.f);
#pragma unroll 8
    for (int i = 0; i < 64; i++) {
        float wv = wp[i];
        float4 m4 = *(const float4*)(mp + (size_t)i * U);
        c.x += wv * m4.x; c.y += wv * m4.y; c.z += wv * m4.z; c.w += wv * m4.w;
    }
    part[tg][u4] = c;
    __syncthreads();

    if (tg == 0) {
        float4 a = part[0][u4], b2 = part[1][u4], c2 = part[2][u4], d2 = part[3][u4];
        float4 r;
        r.x = a.x + b2.x + c2.x + d2.x;
        r.y = a.y + b2.y + c2.y + d2.y;
        r.z = a.z + b2.z + c2.z + d2.z;
        r.w = a.w + b2.w + c2.w + d2.w;
        *(float4*)(g_ctxpart + ((size_t)b * 4 + ch) * U + u4 * 4) = r;
    }
}

// ================= K4: ctx reduce + proj + GRU1 + GRU2 + output head ========
__global__ void k_tail(const float* __restrict__ h1_0, const float* __restrict__ h2_0,
                       const float* __restrict__ projW, const float* __restrict__ projb,
                       const float* __restrict__ g1Wih, const float* __restrict__ g1Whh,
                       const float* __restrict__ g1bih, const float* __restrict__ g1bhh,
                       const float* __restrict__ g2Wih, const float* __restrict__ g2Whh,
                       const float* __restrict__ g2bih, const float* __restrict__ g2bhh,
                       const float* __restrict__ outW, const float* __restrict__ outb,
                       float* __restrict__ d_out) {
    int b = blockIdx.x, j = threadIdx.x;  // 256 threads
    __shared__ float sdt[U], sctx[U], sin1[U], sh1[U], sin2[U], sh2[U], sbf[U];
    sdt[j] = g_dt[b * U + j];
    sctx[j] = g_ctxpart[((size_t)b * 4 + 0) * U + j] + g_ctxpart[((size_t)b * 4 + 1) * U + j]
            + g_ctxpart[((size_t)b * 4 + 2) * U + j] + g_ctxpart[((size_t)b * 4 + 3) * U + j];
    sh1[j] = h1_0[b * U + j];
    sh2[j] = h2_0[b * U + j];
    __syncthreads();

    // proj: gru1_input
    {
        float acc = projb[j];
        const float* wrow = projW + (size_t)j * 2 * U;
#pragma unroll 4
        for (int k = 0; k < U; k++) acc += sdt[k] * wrow[k];
#pragma unroll 4
        for (int k = 0; k < U; k++) acc += sctx[k] * wrow[U + k];
        sin1[j] = acc;
    }
    __syncthreads();

    // GRU1
    {
        float gr = g1bih[j], gz = g1bih[U + j], gn = g1bih[2 * U + j];
        const float* wr = g1Wih + j * U;
        const float* wz = g1Wih + (U + j) * U;
        const float* wn = g1Wih + (2 * U + j) * U;
        float hr = g1bhh[j], hz = g1bhh[U + j], hn = g1bhh[2 * U + j];
        const float* vr = g1Whh + j * U;
        const float* vz = g1Whh + (U + j) * U;
        const float* vn = g1Whh + (2 * U + j) * U;
#pragma unroll 4
        for (int k = 0; k < U; k++) {
            float xv = sin1[k], hv = sh1[k];
            gr += xv * wr[k]; gz += xv * wz[k]; gn += xv * wn[k];
            hr += hv * vr[k]; hz += hv * vz[k]; hn += hv * vn[k];
        }
        float r = sigmoidf_(gr + hr);
        float z = sigmoidf_(gz + hz);
        float n = tanhf(gn + r * hn);
        float h1 = (1.0f - z) * n + z * sh1[j];
        d_out[G1_OFF + b * U + j] = h1;
        sin2[j] = sin1[j] + h1;
    }
    __syncthreads();

    // GRU2
    {
        float gr = g2bih[j], gz = g2bih[U + j], gn = g2bih[2 * U + j];
        const float* wr = g2Wih + j * U;
        const float* wz = g2Wih + (U + j) * U;
        const float* wn = g2Wih + (2 * U + j) * U;
        float hr = g2bhh[j], hz = g2bhh[U + j], hn = g2bhh[2 * U + j];
        const float* vr = g2Whh + j * U;
        const float* vz = g2Whh + (U + j) * U;
        const float* vn = g2Whh + (2 * U + j) * U;
#pragma unroll 4
        for (int k = 0; k < U; k++) {
            float xv = sin2[k], hv = sh2[k];
            gr += xv * wr[k]; gz += xv * wz[k]; gn += xv * wn[k];
            hr += hv * vr[k]; hz += hv * vz[k]; hn += hv * vn[k];
        }
        float r = sigmoidf_(gr + hr);
        float z = sigmoidf_(gz + hz);
        float n = tanhf(gn + r * hn);
        float h2 = (1.0f - z) * n + z * sh2[j];
        d_out[G2_OFF + b * U + j] = h2;
        sbf[j] = sin2[j] + h2;
    }
    __syncthreads();

    // output head: 400 rows
    for (int o = j; o < OUTD; o += 256) {
        float acc = outb[o];
        const float* wrow = outW + (size_t)o * U;
#pragma unroll 4
        for (int k = 0; k < U; k++) acc += sbf[k] * wrow[k];
        d_out[OUT_OFF + b * OUTD + o] = acc;
    }
}

// ================= launch =================
extern "C" void kernel_launch(void* const* d_in, const int* in_sizes, int n_in,
                              void* d_out, int out_size) {
    const float* dec   = (const float*)d_in[0];
    const float* mem   = (const float*)d_in[1];
    const float* ah    = (const float*)d_in[2];
    const float* h1    = (const float*)d_in[3];
    const float* h2    = (const float*)d_in[4];
    const float* W1    = (const float*)d_in[5];
    const float* W2    = (const float*)d_in[6];
    const float* v     = (const float*)d_in[7];
    const float* aWih  = (const float*)d_in[8];
    const float* aWhh  = (const float*)d_in[9];
    const float* abih  = (const float*)d_in[10];
    const float* abhh  = (const float*)d_in[11];
    const float* g1Wih = (const float*)d_in[12];
    const float* g1Whh = (const float*)d_in[13];
    const float* g1bih = (const float*)d_in[14];
    const float* g1bhh = (const float*)d_in[15];
    const float* g2Wih = (const float*)d_in[16];
    const float* g2Whh = (const float*)d_in[17];
    const float* g2bih = (const float*)d_in[18];
    const float* g2bhh = (const float*)d_in[19];
    const float* projW = (const float*)d_in[20];
    const float* projb = (const float*)d_in[21];
    const float* outW  = (const float*)d_in[22];
    const float* outb  = (const float*)d_in[23];
    float* out = (float*)d_out;

    k_transpose<<<dim3(8, 8), dim3(32, 8)>>>(W1);
    k_attn_gru<<<BATCH, 256>>>(dec, ah, aWih, aWhh, abih, abhh, W2, out + DT_OFF);
    k_scores<<<dim3(BATCH, TLEN / 64), 256>>>(mem, v);
    k_softmax_stats<<<BATCH, 256>>>();
    k_context<<<dim3(BATCH, 4), 256>>>(mem);
    k_tail<<<BATCH, 256>>>(h1, h2, projW, projb,
                           g1Wih, g1Whh, g1bih, g1bhh,
                           g2Wih, g2Whh, g2bih, g2bhh, outW, outb, out);
}

// round 6
// speedup vs baseline: 2.2697x; 2.2156x over previous
#include <cuda_runtime.h>
#include <cstdint>
#include <math.h>

#define U 256
#define INWID 128
#define BATCH 128
#define TLEN 1024
#define OUTD 400

// d_out layout: output [B*400] | d_t [B*256] | gru1_h [B*256] | gru2_h [B*256]
#define OUT_OFF 0
#define DT_OFF  (BATCH*OUTD)
#define G1_OFF  (DT_OFF + BATCH*U)
#define G2_OFF  (G1_OFF + BATCH*U)

// -------- scratch (no allocations allowed) --------
__device__ __align__(16) float g_W1t[U * U];
__device__ __align__(16) float g_query[BATCH * U];
__device__ __align__(16) float g_scores[BATCH * TLEN];      // scores, then normalized weights
__device__ __align__(16) float g_ctxpart[BATCH * 4 * U];
__device__ __align__(16) float g_gi[BATCH * 3 * U];         // gate pre-acts (input side)
__device__ __align__(16) float g_gh[BATCH * 3 * U];         // gate pre-acts (hidden side)
__device__ __align__(16) float g_cat[BATCH * 2 * U];        // [d_t | context]
__device__ __align__(16) float g_x1[BATCH * U];             // gru1 input
__device__ __align__(16) float g_x2[BATCH * U];             // gru2 input
__device__ __align__(16) float g_bf[BATCH * U];             // gru2_input + gru2_h

__device__ __forceinline__ float sigmoidf_(float x) {
    return 1.0f / (1.0f + __expf(-x));
}

__device__ __forceinline__ float tanh_fast(float x) {
    float y;
    asm("tanh.approx.f32 %0, %1;" : "=f"(y) : "f"(x));
    return y;
}

__device__ __forceinline__ uint32_t f32_to_tf32(float x) {
    uint32_t r;
    asm("cvt.rna.tf32.f32 %0, %1;" : "=r"(r) : "f"(x));
    return r;
}
__device__ __forceinline__ float tf32v(float x) {
    return __uint_as_float(f32_to_tf32(x));
}

__device__ __forceinline__ void mma_tf32(float c[4], const uint32_t a[4], const uint32_t b[2]) {
    asm volatile(
        "mma.sync.aligned.m16n8k8.row.col.f32.tf32.tf32.f32 "
        "{%0,%1,%2,%3}, {%4,%5,%6,%7}, {%8,%9}, {%0,%1,%2,%3};\n"
        : "+f"(c[0]), "+f"(c[1]), "+f"(c[2]), "+f"(c[3])
        : "r"(a[0]), "r"(a[1]), "r"(a[2]), "r"(a[3]), "r"(b[0]), "r"(b[1]));
}

// ================= K0: W1 [j][k] -> W1t [k][j] =================
__global__ void k_transpose(const float* __restrict__ W1) {
    __shared__ float tile[32][33];
    int k0 = blockIdx.x * 32, j0 = blockIdx.y * 32;
    int tx = threadIdx.x, ty = threadIdx.y;  // 32 x 8
#pragma unroll
    for (int r = 0; r < 32; r += 8)
        tile[ty + r][tx] = W1[(j0 + ty + r) * U + k0 + tx];
    __syncthreads();
#pragma unroll
    for (int r = 0; r < 32; r += 8)
        g_W1t[(k0 + ty + r) * U + j0 + tx] = tile[tx][ty + r];
}

// ================= Generic GEMM: C[128 x N] = A[128 x K] @ W[N x K]^T + bias ==
// Block: 256 threads (8 warps as 4(M) x 2(N) of 32x32 warp tiles). Tile 128x64.
__global__ void __launch_bounds__(256)
k_gemm_tf32(const float* __restrict__ A, int lda,
            const float* __restrict__ W,
            const float* __restrict__ bias,
            float* __restrict__ C, int ldc, int N, int K) {
    int tid = threadIdx.x, lane = tid & 31, w = tid >> 5;
    int n0 = blockIdx.x * 64;

    __shared__ float As[128][36];
    __shared__ float Ws[64][36];

    float acc[2][4][4];
#pragma unroll
    for (int mt = 0; mt < 2; mt++)
#pragma unroll
        for (int nt = 0; nt < 4; nt++)
#pragma unroll
            for (int i = 0; i < 4; i++) acc[mt][nt][i] = 0.0f;

    int mbase = (w & 3) * 32;
    int nbase = (w >> 2) * 32;
    int r0 = lane >> 2, cA = lane & 3;
    int rW = lane >> 2, cW = lane & 3;

    for (int k0 = 0; k0 < K; k0 += 32) {
#pragma unroll
        for (int i = 0; i < 4; i++) {
            int f4 = tid + 256 * i;
            int row = f4 >> 3, c4 = (f4 & 7) * 4;
            float4 v = *(const float4*)(A + (size_t)row * lda + k0 + c4);
            As[row][c4 + 0] = tf32v(v.x);
            As[row][c4 + 1] = tf32v(v.y);
            As[row][c4 + 2] = tf32v(v.z);
            As[row][c4 + 3] = tf32v(v.w);
        }
#pragma unroll
        for (int i = 0; i < 2; i++) {
            int f4 = tid + 256 * i;
            int row = f4 >> 3, c4 = (f4 & 7) * 4;
            int n = n0 + row;
            float4 v = make_float4(0.f, 0.f, 0.f, 0.f);
            if (n < N) v = *(const float4*)(W + (size_t)n * K + k0 + c4);
            Ws[row][c4 + 0] = tf32v(v.x);
            Ws[row][c4 + 1] = tf32v(v.y);
            Ws[row][c4 + 2] = tf32v(v.z);
            Ws[row][c4 + 3] = tf32v(v.w);
        }
        __syncthreads();

#pragma unroll
        for (int kk = 0; kk < 32; kk += 8) {
            uint32_t a[2][4];
#pragma unroll
            for (int mt = 0; mt < 2; mt++) {
                a[mt][0] = __float_as_uint(As[mbase + mt * 16 + r0][kk + cA]);
                a[mt][1] = __float_as_uint(As[mbase + mt * 16 + r0 + 8][kk + cA]);
                a[mt][2] = __float_as_uint(As[mbase + mt * 16 + r0][kk + cA + 4]);
                a[mt][3] = __float_as_uint(As[mbase + mt * 16 + r0 + 8][kk + cA + 4]);
            }
            uint32_t bb[4][2];
#pragma unroll
            for (int nt = 0; nt < 4; nt++) {
                int nl = nbase + nt * 8 + rW;
                bb[nt][0] = __float_as_uint(Ws[nl][kk + cW]);
                bb[nt][1] = __float_as_uint(Ws[nl][kk + cW + 4]);
            }
#pragma unroll
            for (int mt = 0; mt < 2; mt++)
#pragma unroll
                for (int nt = 0; nt < 4; nt++)
                    mma_tf32(acc[mt][nt], a[mt], bb[nt]);
        }
        __syncthreads();
    }

    int q4 = lane & 3;
#pragma unroll
    for (int mt = 0; mt < 2; mt++) {
#pragma unroll
        for (int nt = 0; nt < 4; nt++) {
            int m = mbase + mt * 16 + r0;
            int n = n0 + nbase + nt * 8 + 2 * q4;
            if (n < N) {
                float b0 = bias ? bias[n] : 0.0f;
                float b1 = bias ? bias[n + 1] : 0.0f;
                C[(size_t)m * ldc + n]         = acc[mt][nt][0] + b0;
                C[(size_t)m * ldc + n + 1]     = acc[mt][nt][1] + b1;
                C[(size_t)(m + 8) * ldc + n]     = acc[mt][nt][2] + b0;
                C[(size_t)(m + 8) * ldc + n + 1] = acc[mt][nt][3] + b1;
            }
        }
    }
}

// ================= GRU elementwise combines =================
__device__ __forceinline__ float gru_elem(float gir, float giz, float gin,
                                          float ghr, float ghz, float ghn, float h) {
    float r = sigmoidf_(gir + ghr);
    float z = sigmoidf_(giz + ghz);
    float n = tanhf(gin + r * ghn);
    return (1.0f - z) * n + z * h;
}

__global__ void k_comb_attn(const float* __restrict__ h0, float* __restrict__ dt_out) {
    int b = blockIdx.x, j = threadIdx.x;
    float d = gru_elem(g_gi[b * 768 + j], g_gi[b * 768 + U + j], g_gi[b * 768 + 2 * U + j],
                       g_gh[b * 768 + j], g_gh[b * 768 + U + j], g_gh[b * 768 + 2 * U + j],
                       h0[b * U + j]);
    g_cat[b * 2 * U + j] = d;
    dt_out[b * U + j] = d;
}

__global__ void k_ctx_reduce() {
    int b = blockIdx.x, j = threadIdx.x;
    g_cat[b * 2 * U + U + j] = g_ctxpart[((size_t)b * 4 + 0) * U + j]
                             + g_ctxpart[((size_t)b * 4 + 1) * U + j]
                             + g_ctxpart[((size_t)b * 4 + 2) * U + j]
                             + g_ctxpart[((size_t)b * 4 + 3) * U + j];
}

__global__ void k_comb_g1(const float* __restrict__ h0, float* __restrict__ d_out) {
    int b = blockIdx.x, j = threadIdx.x;
    float h1 = gru_elem(g_gi[b * 768 + j], g_gi[b * 768 + U + j], g_gi[b * 768 + 2 * U + j],
                        g_gh[b * 768 + j], g_gh[b * 768 + U + j], g_gh[b * 768 + 2 * U + j],
                        h0[b * U + j]);
    d_out[G1_OFF + b * U + j] = h1;
    g_x2[b * U + j] = g_x1[b * U + j] + h1;
}

__global__ void k_comb_g2(const float* __restrict__ h0, float* __restrict__ d_out) {
    int b = blockIdx.x, j = threadIdx.x;
    float h2 = gru_elem(g_gi[b * 768 + j], g_gi[b * 768 + U + j], g_gi[b * 768 + 2 * U + j],
                        g_gh[b * 768 + j], g_gh[b * 768 + U + j], g_gh[b * 768 + 2 * U + j],
                        h0[b * U + j]);
    d_out[G2_OFF + b * U + j] = h2;
    g_bf[b * U + j] = g_x2[b * U + j] + h2;
}

// ================= K2: scores = v . tanh(memory@W1^T + query)  (TF32 mma) ====
__global__ void __launch_bounds__(256, 2)
k_scores(const float* __restrict__ memory, const float* __restrict__ v) {
    int b = blockIdx.x;
    int t0 = blockIdx.y * 64;
    int tid = threadIdx.x;
    int lane = tid & 31, w = tid >> 5;

    __shared__ float As[64][36];    // 64 t x 32 k
    __shared__ float Bs[32][264];   // 32 k x 256 j
    __shared__ float sq[U], sv[U];
    __shared__ float spart[64][8];

    sq[tid] = g_query[b * U + tid];
    sv[tid] = v[tid];

    float acc[4][4][4];
#pragma unroll
    for (int mt = 0; mt < 4; mt++)
#pragma unroll
        for (int nt = 0; nt < 4; nt++)
#pragma unroll
            for (int i = 0; i < 4; i++) acc[mt][nt][i] = 0.0f;

    const float* Abase = memory + ((size_t)b * TLEN + t0) * U;

    for (int k0 = 0; k0 < U; k0 += 32) {
#pragma unroll
        for (int i = 0; i < 2; i++) {
            int f4 = tid + 256 * i;
            int row = f4 >> 3, c4 = (f4 & 7) * 4;
            float4 val = *(const float4*)(Abase + row * U + k0 + c4);
            As[row][c4 + 0] = tf32v(val.x);
            As[row][c4 + 1] = tf32v(val.y);
            As[row][c4 + 2] = tf32v(val.z);
            As[row][c4 + 3] = tf32v(val.w);
        }
#pragma unroll
        for (int i = 0; i < 8; i++) {
            int f4 = tid + 256 * i;
            int row = f4 >> 6, c4 = (f4 & 63) * 4;
            float4 val = *(const float4*)(g_W1t + (size_t)(k0 + row) * U + c4);
            Bs[row][c4 + 0] = tf32v(val.x);
            Bs[row][c4 + 1] = tf32v(val.y);
            Bs[row][c4 + 2] = tf32v(val.z);
            Bs[row][c4 + 3] = tf32v(val.w);
        }
        __syncthreads();

        int r0 = lane >> 2, cA = lane & 3;
        int rB = lane & 3, cB = lane >> 2;
#pragma unroll
        for (int kk = 0; kk < 32; kk += 8) {
            uint32_t a[4][4];
#pragma unroll
            for (int mt = 0; mt < 4; mt++) {
                a[mt][0] = __float_as_uint(As[mt * 16 + r0][kk + cA]);
                a[mt][1] = __float_as_uint(As[mt * 16 + r0 + 8][kk + cA]);
                a[mt][2] = __float_as_uint(As[mt * 16 + r0][kk + cA + 4]);
                a[mt][3] = __float_as_uint(As[mt * 16 + r0 + 8][kk + cA + 4]);
            }
            uint32_t bb[4][2];
#pragma unroll
            for (int nt = 0; nt < 4; nt++) {
                int j = w * 32 + nt * 8 + cB;
                bb[nt][0] = __float_as_uint(Bs[kk + rB][j]);
                bb[nt][1] = __float_as_uint(Bs[kk + rB + 4][j]);
            }
#pragma unroll
            for (int mt = 0; mt < 4; mt++)
#pragma unroll
                for (int nt = 0; nt < 4; nt++)
                    mma_tf32(acc[mt][nt], a[mt], bb[nt]);
        }
        __syncthreads();
    }

    // epilogue: v . tanh(key + query)
    float part[8];
#pragma unroll
    for (int i = 0; i < 8; i++) part[i] = 0.0f;
    int r0 = lane >> 2, q4 = lane & 3;
#pragma unroll
    for (int mt = 0; mt < 4; mt++) {
#pragma unroll
        for (int nt = 0; nt < 4; nt++) {
            int j0 = w * 32 + nt * 8 + 2 * q4;
            float q0 = sq[j0], q1 = sq[j0 + 1];
            float v0 = sv[j0], v1 = sv[j0 + 1];
            part[mt * 2 + 0] += v0 * tanh_fast(acc[mt][nt][0] + q0) + v1 * tanh_fast(acc[mt][nt][1] + q1);
            part[mt * 2 + 1] += v0 * tanh_fast(acc[mt][nt][2] + q0) + v1 * tanh_fast(acc[mt][nt][3] + q1);
        }
    }
#pragma unroll
    for (int i = 0; i < 8; i++) {
        part[i] += __shfl_xor_sync(0xffffffffu, part[i], 1);
        part[i] += __shfl_xor_sync(0xffffffffu, part[i], 2);
    }
    if ((lane & 3) == 0) {
#pragma unroll
        for (int mt = 0; mt < 4; mt++) {
            spart[mt * 16 + r0][w] = part[mt * 2 + 0];
            spart[mt * 16 + r0 + 8][w] = part[mt * 2 + 1];
        }
    }
    __syncthreads();
    if (tid < 64) {
        float s = 0.0f;
#pragma unroll
        for (int i = 0; i < 8; i++) s += spart[tid][i];
        g_scores[b * TLEN + t0 + tid] = s;
    }
}

// ================= K3a: softmax stats; normalize in place =================
__global__ void k_softmax_stats() {
    int b = blockIdx.x;
    int tid = threadIdx.x;  // 256 threads, 4 scores each
    int lane = tid & 31, warp = tid >> 5;
    __shared__ float red[8];

    float4 s = *(const float4*)(g_scores + b * TLEN + tid * 4);
    float m = fmaxf(fmaxf(s.x, s.y), fmaxf(s.z, s.w));
#pragma unroll
    for (int off = 16; off; off >>= 1) m = fmaxf(m, __shfl_xor_sync(0xffffffffu, m, off));
    if (lane == 0) red[warp] = m;
    __syncthreads();
    if (tid == 0) {
        float mm = red[0];
#pragma unroll
        for (int i = 1; i < 8; i++) mm = fmaxf(mm, red[i]);
        red[0] = mm;
    }
    __syncthreads();
    float mx = red[0];
    __syncthreads();

    float4 e;
    e.x = __expf(s.x - mx); e.y = __expf(s.y - mx);
    e.z = __expf(s.z - mx); e.w = __expf(s.w - mx);
    float t = e.x + e.y + e.z + e.w;
#pragma unroll
    for (int off = 16; off; off >>= 1) t += __shfl_xor_sync(0xffffffffu, t, off);
    if (lane == 0) red[warp] = t;
    __syncthreads();
    if (tid == 0) {
        float ss = 0.0f;
#pragma unroll
        for (int i = 0; i < 8; i++) ss += red[i];
        red[0] = 1.0f / ss;
    }
    __syncthreads();
    float inv = red[0];
    e.x *= inv; e.y *= inv; e.z *= inv; e.w *= inv;
    *(float4*)(g_scores + b * TLEN + tid * 4) = e;
}

// ================= K3b: context partials (grid B x 4) =================
__global__ void __launch_bounds__(256, 4)
k_context(const float* __restrict__ memory) {
    int b = blockIdx.x, ch = blockIdx.y;
    int tid = threadIdx.x;
    int u4 = tid & 63;
    int tg = tid >> 6;

    __shared__ float sw[256];
    __shared__ float4 part[4][64];

    sw[tid] = g_scores[b * TLEN + ch * 256 + tid];
    __syncthreads();

    const float* mp = memory + ((size_t)b * TLEN + ch * 256 + tg * 64) * U + u4 * 4;
    const float* wp = sw + tg * 64;
    float4 c = make_float4(0.f, 0.f, 0.f, 0.f);
#pragma unroll 8
    for (int i = 0; i < 64; i++) {
        float wv = wp[i];
        float4 m4 = *(const float4*)(mp + (size_t)i * U);
        c.x += wv * m4.x; c.y += wv * m4.y; c.z += wv * m4.z; c.w += wv * m4.w;
    }
    part[tg][u4] = c;
    __syncthreads();

    if (tg == 0) {
        float4 a = part[0][u4], b2 = part[1][u4], c2 = part[2][u4], d2 = part[3][u4];
        float4 r;
        r.x = a.x + b2.x + c2.x + d2.x;
        r.y = a.y + b2.y + c2.y + d2.y;
        r.z = a.z + b2.z + c2.z + d2.z;
        r.w = a.w + b2.w + c2.w + d2.w;
        *(float4*)(g_ctxpart + ((size_t)b * 4 + ch) * U + u4 * 4) = r;
    }
}

// ================= launch =================
extern "C" void kernel_launch(void* const* d_in, const int* in_sizes, int n_in,
                              void* d_out, int out_size) {
    const float* dec   = (const float*)d_in[0];
    const float* mem   = (const float*)d_in[1];
    const float* ah    = (const float*)d_in[2];
    const float* h1    = (const float*)d_in[3];
    const float* h2    = (const float*)d_in[4];
    const float* W1    = (const float*)d_in[5];
    const float* W2    = (const float*)d_in[6];
    const float* v     = (const float*)d_in[7];
    const float* aWih  = (const float*)d_in[8];
    const float* aWhh  = (const float*)d_in[9];
    const float* abih  = (const float*)d_in[10];
    const float* abhh  = (const float*)d_in[11];
    const float* g1Wih = (const float*)d_in[12];
    const float* g1Whh = (const float*)d_in[13];
    const float* g1bih = (const float*)d_in[14];
    const float* g1bhh = (const float*)d_in[15];
    const float* g2Wih = (const float*)d_in[16];
    const float* g2Whh = (const float*)d_in[17];
    const float* g2bih = (const float*)d_in[18];
    const float* g2bhh = (const float*)d_in[19];
    const float* projW = (const float*)d_in[20];
    const float* projb = (const float*)d_in[21];
    const float* outW  = (const float*)d_in[22];
    const float* outb  = (const float*)d_in[23];
    float* out = (float*)d_out;

    float* p_gi;    cudaGetSymbolAddress((void**)&p_gi, g_gi);
    float* p_gh;    cudaGetSymbolAddress((void**)&p_gh, g_gh);
    float* p_cat;   cudaGetSymbolAddress((void**)&p_cat, g_cat);
    float* p_x1;    cudaGetSymbolAddress((void**)&p_x1, g_x1);
    float* p_x2;    cudaGetSymbolAddress((void**)&p_x2, g_x2);
    float* p_bf;    cudaGetSymbolAddress((void**)&p_bf, g_bf);
    float* p_query; cudaGetSymbolAddress((void**)&p_query, g_query);

    k_transpose<<<dim3(8, 8), dim3(32, 8)>>>(W1);

    // attention GRU cell via batched GEMMs
    k_gemm_tf32<<<12, 256>>>(dec, INWID, aWih, abih, p_gi, 768, 768, INWID);
    k_gemm_tf32<<<12, 256>>>(ah, U, aWhh, abhh, p_gh, 768, 768, U);
    k_comb_attn<<<BATCH, 256>>>(ah, out + DT_OFF);

    // query = d_t @ W2^T   (d_t lives in g_cat cols [0,256), lda=512)
    k_gemm_tf32<<<4, 256>>>(p_cat, 2 * U, W2, nullptr, p_query, U, U, U);

    k_scores<<<dim3(BATCH, TLEN / 64), 256>>>(mem, v);
    k_softmax_stats<<<BATCH, 256>>>();
    k_context<<<dim3(BATCH, 4), 256>>>(mem);
    k_ctx_reduce<<<BATCH, 256>>>();

    // gru1_input = [d_t | ctx] @ projW^T + projb
    k_gemm_tf32<<<4, 256>>>(p_cat, 2 * U, projW, projb, p_x1, U, U, 2 * U);

    // GRU1
    k_gemm_tf32<<<12, 256>>>(p_x1, U, g1Wih, g1bih, p_gi, 768, 768, U);
    k_gemm_tf32<<<12, 256>>>(h1, U, g1Whh, g1bhh, p_gh, 768, 768, U);
    k_comb_g1<<<BATCH, 256>>>(h1, out);

    // GRU2
    k_gemm_tf32<<<12, 256>>>(p_x2, U, g2Wih, g2bih, p_gi, 768, 768, U);
    k_gemm_tf32<<<12, 256>>>(h2, U, g2Whh, g2bhh, p_gh, 768, 768, U);
    k_comb_g2<<<BATCH, 256>>>(h2, out);

    // output head
    k_gemm_tf32<<<7, 256>>>(p_bf, U, outW, outb, out + OUT_OFF, OUTD, OUTD, U);
}

// round 11
// speedup vs baseline: 2.9685x; 1.3079x over previous
#include <cuda_runtime.h>
#include <cstdint>
#include <math.h>

#define U 256
#define INWID 128
#define BATCH 128
#define TLEN 1024
#define OUTD 400

// d_out layout: output [B*400] | d_t [B*256] | gru1_h [B*256] | gru2_h [B*256]
#define OUT_OFF 0
#define DT_OFF  (BATCH*OUTD)
#define G1_OFF  (DT_OFF + BATCH*U)
#define G2_OFF  (G1_OFF + BATCH*U)

// -------- scratch (no allocations allowed) --------
__device__ __align__(16) float g_W1tp[256 * 264];   // tf32, transposed, padded rows
__device__ __align__(16) float g_query[BATCH * U];
__device__ __align__(16) float g_scores[BATCH * TLEN];
__device__ __align__(16) float g_ctxpart[BATCH * 4 * U];
__device__ __align__(16) float g_giA[BATCH * 3 * U];
__device__ __align__(16) float g_ghA[BATCH * 3 * U];
__device__ __align__(16) float g_gh1[BATCH * 3 * U];
__device__ __align__(16) float g_gh2[BATCH * 3 * U];
__device__ __align__(16) float g_gi12[BATCH * 3 * U];
__device__ __align__(16) float g_cat[BATCH * 2 * U];
__device__ __align__(16) float g_x1[BATCH * U];
__device__ __align__(16) float g_x2[BATCH * U];
__device__ __align__(16) float g_bf[BATCH * U];

__device__ __forceinline__ float sigmoidf_(float x) {
    return 1.0f / (1.0f + __expf(-x));
}
__device__ __forceinline__ float tanh_fast(float x) {
    float y;
    asm("tanh.approx.f32 %0, %1;" : "=f"(y) : "f"(x));
    return y;
}
__device__ __forceinline__ uint32_t f32_to_tf32(float x) {
    uint32_t r;
    asm("cvt.rna.tf32.f32 %0, %1;" : "=r"(r) : "f"(x));
    return r;
}
__device__ __forceinline__ float tf32v(float x) {
    return __uint_as_float(f32_to_tf32(x));
}
__device__ __forceinline__ void mma_tf32(float c[4], const uint32_t a[4], const uint32_t b[2]) {
    asm volatile(
        "mma.sync.aligned.m16n8k8.row.col.f32.tf32.tf32.f32 "
        "{%0,%1,%2,%3}, {%4,%5,%6,%7}, {%8,%9}, {%0,%1,%2,%3};\n"
        : "+f"(c[0]), "+f"(c[1]), "+f"(c[2]), "+f"(c[3])
        : "r"(a[0]), "r"(a[1]), "r"(a[2]), "r"(a[3]), "r"(b[0]), "r"(b[1]));
}
__device__ __forceinline__ uint32_t smem_u32(const void* p) {
    uint32_t a;
    asm("{ .reg .u64 t; cvta.to.shared.u64 t, %1; cvt.u32.u64 %0, t; }" : "=r"(a) : "l"(p));
    return a;
}
__device__ __forceinline__ void cp_async16(uint32_t dst, const void* src) {
    asm volatile("cp.async.ca.shared.global [%0], [%1], 16;\n" :: "r"(dst), "l"(src));
}
__device__ __forceinline__ void cp_commit() {
    asm volatile("cp.async.commit_group;\n");
}
__device__ __forceinline__ void cp_wait1() {
    asm volatile("cp.async.wait_group 1;\n" ::: "memory");
}
__device__ __forceinline__ void cp_wait0() {
    asm volatile("cp.async.wait_group 0;\n" ::: "memory");
}

// ================= prep: W1 [j][k] -> W1tp [k][j] (tf32, 264-stride) ========
__global__ void k_prepW1(const float* __restrict__ W1) {
    __shared__ float tile[32][33];
    int k0 = blockIdx.x * 32, j0 = blockIdx.y * 32;
    int tx = threadIdx.x, ty = threadIdx.y;  // 32 x 8
#pragma unroll
    for (int r = 0; r < 32; r += 8)
        tile[ty + r][tx] = W1[(j0 + ty + r) * U + k0 + tx];
    __syncthreads();
#pragma unroll
    for (int r = 0; r < 32; r += 8)
        g_W1tp[(size_t)(k0 + ty + r) * 264 + j0 + tx] = tf32v(tile[tx][ty + r]);
}

// ================= K2: scores via pipelined tf32 mma =================
// Tile: M=128 t-rows x N=256 j, K=256 in 8 chunks of 32. Grid (B, T/128).
// 8 warps: 2(M) x 4(N), warp tile 64x64.
__global__ void __launch_bounds__(256, 1)
k_scores3(const float* __restrict__ memory, const float* __restrict__ v) {
    extern __shared__ float dsm[];
    // As[2][128][36] then Bs[2][32][264]
    float* Abuf = dsm;                         // 2 * 4608 floats
    float* Bbuf = dsm + 2 * 128 * 36;          // 2 * 8448 floats
    __shared__ float sq[U], sv[U];
    __shared__ float spart[128][4];

    int b = blockIdx.x, t0 = blockIdx.y * 128;
    int tid = threadIdx.x, lane = tid & 31, w = tid >> 5;

    sq[tid] = g_query[b * U + tid];
    sv[tid] = v[tid];

    const float* Abase = memory + ((size_t)b * TLEN + t0) * U;

    int mbase = (w & 1) * 64;
    int nbase = (w >> 1) * 64;
    int r0 = lane >> 2, cA = lane & 3;
    int rB = lane & 3, cB = lane >> 2;

    float acc[4][8][4];
#pragma unroll
    for (int mt = 0; mt < 4; mt++)
#pragma unroll
        for (int nt = 0; nt < 8; nt++)
#pragma unroll
            for (int i = 0; i < 4; i++) acc[mt][nt][i] = 0.0f;

    // ---- prologue: stage chunk 0 into buf 0 ----
    // A chunk: 128 rows x 32 floats = 1024 float4 (8 float4 per row)
#pragma unroll
    for (int i = 0; i < 4; i++) {
        int u = tid + 256 * i;
        int row = u >> 3, c4 = (u & 7) * 4;
        cp_async16(smem_u32(Abuf + row * 36 + c4), Abase + (size_t)row * U + c4);
    }
    // B chunk: 32 rows x 256 floats = 2048 float4 (64 float4 per row)
#pragma unroll
    for (int i = 0; i < 8; i++) {
        int u = tid + 256 * i;
        int row = u >> 6, c4 = (u & 63) * 4;
        cp_async16(smem_u32(Bbuf + row * 264 + c4), g_W1tp + (size_t)row * 264 + c4);
    }
    cp_commit();

    for (int kc = 0; kc < 8; kc++) {
        int buf = kc & 1;
        if (kc < 7) {
            float* An = Abuf + (buf ^ 1) * 4608;
            float* Bn = Bbuf + (buf ^ 1) * 8448;
#pragma unroll
            for (int i = 0; i < 4; i++) {
                int u = tid + 256 * i;
                int row = u >> 3, c4 = (u & 7) * 4;
                cp_async16(smem_u32(An + row * 36 + c4),
                           Abase + (size_t)row * U + (kc + 1) * 32 + c4);
            }
#pragma unroll
            for (int i = 0; i < 8; i++) {
                int u = tid + 256 * i;
                int row = u >> 6, c4 = (u & 63) * 4;
                cp_async16(smem_u32(Bn + row * 264 + c4),
                           g_W1tp + (size_t)((kc + 1) * 32 + row) * 264 + c4);
            }
            cp_commit();
            cp_wait1();
        } else {
            cp_wait0();
        }
        __syncthreads();

        const float* Ac = Abuf + buf * 4608;
        const float* Bc = Bbuf + buf * 8448;
#pragma unroll
        for (int kk = 0; kk < 32; kk += 8) {
            uint32_t a[4][4];
#pragma unroll
            for (int mt = 0; mt < 4; mt++) {
                a[mt][0] = f32_to_tf32(Ac[(mbase + mt * 16 + r0) * 36 + kk + cA]);
                a[mt][1] = f32_to_tf32(Ac[(mbase + mt * 16 + r0 + 8) * 36 + kk + cA]);
                a[mt][2] = f32_to_tf32(Ac[(mbase + mt * 16 + r0) * 36 + kk + cA + 4]);
                a[mt][3] = f32_to_tf32(Ac[(mbase + mt * 16 + r0 + 8) * 36 + kk + cA + 4]);
            }
            uint32_t bb[8][2];
#pragma unroll
            for (int nt = 0; nt < 8; nt++) {
                int j = nbase + nt * 8 + cB;
                bb[nt][0] = __float_as_uint(Bc[(kk + rB) * 264 + j]);
                bb[nt][1] = __float_as_uint(Bc[(kk + rB + 4) * 264 + j]);
            }
#pragma unroll
            for (int mt = 0; mt < 4; mt++)
#pragma unroll
                for (int nt = 0; nt < 8; nt++)
                    mma_tf32(acc[mt][nt], a[mt], bb[nt]);
        }
        __syncthreads();
    }

    // ---- epilogue: score[row] = sum_j v_j * tanh(D[row][j] + q_j) ----
    float part[8];
#pragma unroll
    for (int i = 0; i < 8; i++) part[i] = 0.0f;
    int q4 = lane & 3;
#pragma unroll
    for (int mt = 0; mt < 4; mt++) {
#pragma unroll
        for (int nt = 0; nt < 8; nt++) {
            int j0 = nbase + nt * 8 + 2 * q4;
            float q0 = sq[j0], q1 = sq[j0 + 1];
            float v0 = sv[j0], v1 = sv[j0 + 1];
            part[mt * 2 + 0] += v0 * tanh_fast(acc[mt][nt][0] + q0) + v1 * tanh_fast(acc[mt][nt][1] + q1);
            part[mt * 2 + 1] += v0 * tanh_fast(acc[mt][nt][2] + q0) + v1 * tanh_fast(acc[mt][nt][3] + q1);
        }
    }
#pragma unroll
    for (int i = 0; i < 8; i++) {
        part[i] += __shfl_xor_sync(0xffffffffu, part[i], 1);
        part[i] += __shfl_xor_sync(0xffffffffu, part[i], 2);
    }
    if ((lane & 3) == 0) {
#pragma unroll
        for (int mt = 0; mt < 4; mt++) {
            spart[mbase + mt * 16 + r0][w >> 1] = part[mt * 2 + 0];
            spart[mbase + mt * 16 + r0 + 8][w >> 1] = part[mt * 2 + 1];
        }
    }
    __syncthreads();
    if (tid < 128) {
        float s = spart[tid][0] + spart[tid][1] + spart[tid][2] + spart[tid][3];
        g_scores[b * TLEN + t0 + tid] = s;
    }
}

// ================= Generic GEMM body: C[128 x N] = A @ W^T + bias ==========
__device__ __forceinline__ void gemm_body(const float* __restrict__ A, int lda,
                                          const float* __restrict__ W,
                                          const float* __restrict__ bias,
                                          float* __restrict__ C, int ldc,
                                          int N, int K, int n0) {
    int tid = threadIdx.x, lane = tid & 31, w = tid >> 5;

    __shared__ float As[128][36];
    __shared__ float Ws[64][36];

    float acc[2][4][4];
#pragma unroll
    for (int mt = 0; mt < 2; mt++)
#pragma unroll
        for (int nt = 0; nt < 4; nt++)
#pragma unroll
            for (int i = 0; i < 4; i++) acc[mt][nt][i] = 0.0f;

    int mbase = (w & 3) * 32;
    int nbase = (w >> 2) * 32;
    int r0 = lane >> 2, cA = lane & 3;
    int rW = lane >> 2, cW = lane & 3;

    for (int k0 = 0; k0 < K; k0 += 32) {
#pragma unroll
        for (int i = 0; i < 4; i++) {
            int f4 = tid + 256 * i;
            int row = f4 >> 3, c4 = (f4 & 7) * 4;
            float4 v = *(const float4*)(A + (size_t)row * lda + k0 + c4);
            As[row][c4 + 0] = tf32v(v.x);
            As[row][c4 + 1] = tf32v(v.y);
            As[row][c4 + 2] = tf32v(v.z);
            As[row][c4 + 3] = tf32v(v.w);
        }
#pragma unroll
        for (int i = 0; i < 2; i++) {
            int f4 = tid + 256 * i;
            int row = f4 >> 3, c4 = (f4 & 7) * 4;
            int n = n0 + row;
            float4 v = make_float4(0.f, 0.f, 0.f, 0.f);
            if (n < N) v = *(const float4*)(W + (size_t)n * K + k0 + c4);
            Ws[row][c4 + 0] = tf32v(v.x);
            Ws[row][c4 + 1] = tf32v(v.y);
            Ws[row][c4 + 2] = tf32v(v.z);
            Ws[row][c4 + 3] = tf32v(v.w);
        }
        __syncthreads();

#pragma unroll
        for (int kk = 0; kk < 32; kk += 8) {
            uint32_t a[2][4];
#pragma unroll
            for (int mt = 0; mt < 2; mt++) {
                a[mt][0] = __float_as_uint(As[mbase + mt * 16 + r0][kk + cA]);
                a[mt][1] = __float_as_uint(As[mbase + mt * 16 + r0 + 8][kk + cA]);
                a[mt][2] = __float_as_uint(As[mbase + mt * 16 + r0][kk + cA + 4]);
                a[mt][3] = __float_as_uint(As[mbase + mt * 16 + r0 + 8][kk + cA + 4]);
            }
            uint32_t bb[4][2];
#pragma unroll
            for (int nt = 0; nt < 4; nt++) {
                int nl = nbase + nt * 8 + rW;
                bb[nt][0] = __float_as_uint(Ws[nl][kk + cW]);
                bb[nt][1] = __float_as_uint(Ws[nl][kk + cW + 4]);
            }
#pragma unroll
            for (int mt = 0; mt < 2; mt++)
#pragma unroll
                for (int nt = 0; nt < 4; nt++)
                    mma_tf32(acc[mt][nt], a[mt], bb[nt]);
        }
        __syncthreads();
    }

    int q4 = lane & 3;
#pragma unroll
    for (int mt = 0; mt < 2; mt++) {
#pragma unroll
        for (int nt = 0; nt < 4; nt++) {
            int m = mbase + mt * 16 + r0;
            int n = n0 + nbase + nt * 8 + 2 * q4;
            if (n < N) {
                float b0 = bias ? bias[n] : 0.0f;
                float b1 = bias ? bias[n + 1] : 0.0f;
                C[(size_t)m * ldc + n]           = acc[mt][nt][0] + b0;
                C[(size_t)m * ldc + n + 1]       = acc[mt][nt][1] + b1;
                C[(size_t)(m + 8) * ldc + n]     = acc[mt][nt][2] + b0;
                C[(size_t)(m + 8) * ldc + n + 1] = acc[mt][nt][3] + b1;
            }
        }
    }
}

__global__ void __launch_bounds__(256)
k_gemm_tf32(const float* __restrict__ A, int lda, const float* __restrict__ W,
            const float* __restrict__ bias, float* __restrict__ C, int ldc,
            int N, int K) {
    gemm_body(A, lda, W, bias, C, ldc, N, K, blockIdx.x * 64);
}

struct GemmJob {
    const float* A; const float* W; const float* bias; float* C;
    int lda; int ldc; int N; int K;
};
struct GemmJobs4 { GemmJob j[4]; };

__global__ void __launch_bounds__(256)
k_gemm_multi(GemmJobs4 jobs) {
    GemmJob jb = jobs.j[blockIdx.y];
    gemm_body(jb.A, jb.lda, jb.W, jb.bias, jb.C, jb.ldc, jb.N, jb.K, blockIdx.x * 64);
}

// ================= GRU elementwise combines =================
__device__ __forceinline__ float gru_elem(float gir, float giz, float gin,
                                          float ghr, float ghz, float ghn, float h) {
    float r = sigmoidf_(gir + ghr);
    float z = sigmoidf_(giz + ghz);
    float n = tanhf(gin + r * ghn);
    return (1.0f - z) * n + z * h;
}

__global__ void k_comb_attn(const float* __restrict__ gi, const float* __restrict__ gh,
                            const float* __restrict__ h0, float* __restrict__ dt_out) {
    int b = blockIdx.x, j = threadIdx.x;
    float d = gru_elem(gi[b * 768 + j], gi[b * 768 + U + j], gi[b * 768 + 2 * U + j],
                       gh[b * 768 + j], gh[b * 768 + U + j], gh[b * 768 + 2 * U + j],
                       h0[b * U + j]);
    g_cat[b * 2 * U + j] = d;
    dt_out[b * U + j] = d;
}

__global__ void k_ctx_reduce() {
    int b = blockIdx.x, j = threadIdx.x;
    g_cat[b * 2 * U + U + j] = g_ctxpart[((size_t)b * 4 + 0) * U + j]
                             + g_ctxpart[((size_t)b * 4 + 1) * U + j]
                             + g_ctxpart[((size_t)b * 4 + 2) * U + j]
                             + g_ctxpart[((size_t)b * 4 + 3) * U + j];
}

__global__ void k_comb_g1(const float* __restrict__ gi, const float* __restrict__ gh,
                          const float* __restrict__ h0, float* __restrict__ d_out) {
    int b = blockIdx.x, j = threadIdx.x;
    float h1 = gru_elem(gi[b * 768 + j], gi[b * 768 + U + j], gi[b * 768 + 2 * U + j],
                        gh[b * 768 + j], gh[b * 768 + U + j], gh[b * 768 + 2 * U + j],
                        h0[b * U + j]);
    d_out[G1_OFF + b * U + j] = h1;
    g_x2[b * U + j] = g_x1[b * U + j] + h1;
}

__global__ void k_comb_g2(const float* __restrict__ gi, const float* __restrict__ gh,
                          const float* __restrict__ h0, float* __restrict__ d_out) {
    int b = blockIdx.x, j = threadIdx.x;
    float h2 = gru_elem(gi[b * 768 + j], gi[b * 768 + U + j], gi[b * 768 + 2 * U + j],
                        gh[b * 768 + j], gh[b * 768 + U + j], gh[b * 768 + 2 * U + j],
                        h0[b * U + j]);
    d_out[G2_OFF + b * U + j] = h2;
    g_bf[b * U + j] = g_x2[b * U + j] + h2;
}

// ================= softmax stats; normalize in place =================
__global__ void k_softmax_stats() {
    int b = blockIdx.x;
    int tid = threadIdx.x;
    int lane = tid & 31, warp = tid >> 5;
    __shared__ float red[8];

    float4 s = *(const float4*)(g_scores + b * TLEN + tid * 4);
    float m = fmaxf(fmaxf(s.x, s.y), fmaxf(s.z, s.w));
#pragma unroll
    for (int off = 16; off; off >>= 1) m = fmaxf(m, __shfl_xor_sync(0xffffffffu, m, off));
    if (lane == 0) red[warp] = m;
    __syncthreads();
    if (tid == 0) {
        float mm = red[0];
#pragma unroll
        for (int i = 1; i < 8; i++) mm = fmaxf(mm, red[i]);
        red[0] = mm;
    }
    __syncthreads();
    float mx = red[0];
    __syncthreads();

    float4 e;
    e.x = __expf(s.x - mx); e.y = __expf(s.y - mx);
    e.z = __expf(s.z - mx); e.w = __expf(s.w - mx);
    float t = e.x + e.y + e.z + e.w;
#pragma unroll
    for (int off = 16; off; off >>= 1) t += __shfl_xor_sync(0xffffffffu, t, off);
    if (lane == 0) red[warp] = t;
    __syncthreads();
    if (tid == 0) {
        float ss = 0.0f;
#pragma unroll
        for (int i = 0; i < 8; i++) ss += red[i];
        red[0] = 1.0f / ss;
    }
    __syncthreads();
    float inv = red[0];
    e.x *= inv; e.y *= inv; e.z *= inv; e.w *= inv;
    *(float4*)(g_scores + b * TLEN + tid * 4) = e;
}

// ================= context partials (grid B x 4) =================
__global__ void __launch_bounds__(256, 4)
k_context(const float* __restrict__ memory) {
    int b = blockIdx.x, ch = blockIdx.y;
    int tid = threadIdx.x;
    int u4 = tid & 63;
    int tg = tid >> 6;

    __shared__ float sw[256];
    __shared__ float4 part[4][64];

    sw[tid] = g_scores[b * TLEN + ch * 256 + tid];
    __syncthreads();

    const float* mp = memory + ((size_t)b * TLEN + ch * 256 + tg * 64) * U + u4 * 4;
    const float* wp = sw + tg * 64;
    float4 c = make_float4(0.f, 0.f, 0.f, 0.f);
#pragma unroll 8
    for (int i = 0; i < 64; i++) {
        float wv = wp[i];
        float4 m4 = *(const float4*)(mp + (size_t)i * U);
        c.x += wv * m4.x; c.y += wv * m4.y; c.z += wv * m4.z; c.w += wv * m4.w;
    }
    part[tg][u4] = c;
    __syncthreads();

    if (tg == 0) {
        float4 a = part[0][u4], b2 = part[1][u4], c2 = part[2][u4], d2 = part[3][u4];
        float4 r;
        r.x = a.x + b2.x + c2.x + d2.x;
        r.y = a.y + b2.y + c2.y + d2.y;
        r.z = a.z + b2.z + c2.z + d2.z;
        r.w = a.w + b2.w + c2.w + d2.w;
        *(float4*)(g_ctxpart + ((size_t)b * 4 + ch) * U + u4 * 4) = r;
    }
}

// ================= launch =================
extern "C" void kernel_launch(void* const* d_in, const int* in_sizes, int n_in,
                              void* d_out, int out_size) {
    const float* dec   = (const float*)d_in[0];
    const float* mem   = (const float*)d_in[1];
    const float* ah    = (const float*)d_in[2];
    const float* h1    = (const float*)d_in[3];
    const float* h2    = (const float*)d_in[4];
    const float* W1    = (const float*)d_in[5];
    const float* W2    = (const float*)d_in[6];
    const float* v     = (const float*)d_in[7];
    const float* aWih  = (const float*)d_in[8];
    const float* aWhh  = (const float*)d_in[9];
    const float* abih  = (const float*)d_in[10];
    const float* abhh  = (const float*)d_in[11];
    const float* g1Wih = (const float*)d_in[12];
    const float* g1Whh = (const float*)d_in[13];
    const float* g1bih = (const float*)d_in[14];
    const float* g1bhh = (const float*)d_in[15];
    const float* g2Wih = (const float*)d_in[16];
    const float* g2Whh = (const float*)d_in[17];
    const float* g2bih = (const float*)d_in[18];
    const float* g2bhh = (const float*)d_in[19];
    const float* projW = (const float*)d_in[20];
    const float* projb = (const float*)d_in[21];
    const float* outW  = (const float*)d_in[22];
    const float* outb  = (const float*)d_in[23];
    float* out = (float*)d_out;

    float* p_giA;   cudaGetSymbolAddress((void**)&p_giA, g_giA);
    float* p_ghA;   cudaGetSymbolAddress((void**)&p_ghA, g_ghA);
    float* p_gh1;   cudaGetSymbolAddress((void**)&p_gh1, g_gh1);
    float* p_gh2;   cudaGetSymbolAddress((void**)&p_gh2, g_gh2);
    float* p_gi12;  cudaGetSymbolAddress((void**)&p_gi12, g_gi12);
    float* p_cat;   cudaGetSymbolAddress((void**)&p_cat, g_cat);
    float* p_x1;    cudaGetSymbolAddress((void**)&p_x1, g_x1);
    float* p_x2;    cudaGetSymbolAddress((void**)&p_x2, g_x2);
    float* p_bf;    cudaGetSymbolAddress((void**)&p_bf, g_bf);
    float* p_query; cudaGetSymbolAddress((void**)&p_query, g_query);

    static int smem_set = 0;
    const int SC_SMEM = (2 * 128 * 36 + 2 * 32 * 264) * 4;   // 104448 B
    if (!smem_set) {
        cudaFuncSetAttribute(k_scores3, cudaFuncAttributeMaxDynamicSharedMemorySize, SC_SMEM);
        smem_set = 1;
    }

    k_prepW1<<<dim3(8, 8), dim3(32, 8)>>>(W1);

    // batch the 4 input-independent gate GEMMs into one launch
    GemmJobs4 jobs;
    jobs.j[0] = { dec, aWih,  abih,  p_giA, INWID, 768, 768, INWID };
    jobs.j[1] = { ah,  aWhh,  abhh,  p_ghA, U,     768, 768, U     };
    jobs.j[2] = { h1,  g1Whh, g1bhh, p_gh1, U,     768, 768, U     };
    jobs.j[3] = { h2,  g2Whh, g2bhh, p_gh2, U,     768, 768, U     };
    k_gemm_multi<<<dim3(12, 4), 256>>>(jobs);

    k_comb_attn<<<BATCH, 256>>>(p_giA, p_ghA, ah, out + DT_OFF);

    // query = d_t @ W2^T   (d_t is g_cat cols [0,256), lda=512)
    k_gemm_tf32<<<4, 256>>>(p_cat, 2 * U, W2, nullptr, p_query, U, U, U);

    k_scores3<<<dim3(BATCH, TLEN / 128), 256, SC_SMEM>>>(mem, v);
    k_softmax_stats<<<BATCH, 256>>>();
    k_context<<<dim3(BATCH, 4), 256>>>(mem);
    k_ctx_reduce<<<BATCH, 256>>>();

    // gru1_input = [d_t | ctx] @ projW^T + projb
    k_gemm_tf32<<<4, 256>>>(p_cat, 2 * U, projW, projb, p_x1, U, U, 2 * U);

    // GRU1 input-side + combine
    k_gemm_tf32<<<12, 256>>>(p_x1, U, g1Wih, g1bih, p_gi12, 768, 768, U);
    k_comb_g1<<<BATCH, 256>>>(p_gi12, p_gh1, h1, out);

    // GRU2 input-side + combine
    k_gemm_tf32<<<12, 256>>>(p_x2, U, g2Wih, g2bih, p_gi12, 768, 768, U);
    k_comb_g2<<<BATCH, 256>>>(p_gi12, p_gh2, h2, out);

    // output head
    k_gemm_tf32<<<7, 256>>>(p_bf, U, outW, outb, out + OUT_OFF, OUTD, OUTD, U);
}

// round 12
// speedup vs baseline: 4.0786x; 1.3740x over previous
#include <cuda_runtime.h>
#include <cstdint>
#include <math.h>

#define U 256
#define INWID 128
#define BATCH 128
#define TLEN 1024
#define OUTD 400

// d_out layout: output [B*400] | d_t [B*256] | gru1_h [B*256] | gru2_h [B*256]
#define OUT_OFF 0
#define DT_OFF  (BATCH*OUTD)
#define G1_OFF  (DT_OFF + BATCH*U)
#define G2_OFF  (G1_OFF + BATCH*U)

// -------- scratch (no allocations allowed) --------
__device__ __align__(16) float g_W1tp[256 * 264];   // tf32, transposed, padded rows
__device__ __align__(16) float g_query[BATCH * U];
__device__ __align__(16) float g_scores[BATCH * TLEN];
__device__ __align__(16) float g_ctxpart[BATCH * 4 * U];
__device__ __align__(16) float g_ghA[BATCH * 3 * U];
__device__ __align__(16) float g_gh1[BATCH * 3 * U];
__device__ __align__(16) float g_gh2[BATCH * 3 * U];
__device__ __align__(16) float g_cat[BATCH * 2 * U];
__device__ __align__(16) float g_x1[BATCH * U];
__device__ __align__(16) float g_x2[BATCH * U];
__device__ __align__(16) float g_bf[BATCH * U];

__device__ __forceinline__ float sigmoidf_(float x) {
    return 1.0f / (1.0f + __expf(-x));
}
__device__ __forceinline__ float tanh_fast(float x) {
    float y;
    asm("tanh.approx.f32 %0, %1;" : "=f"(y) : "f"(x));
    return y;
}
__device__ __forceinline__ uint32_t f32_to_tf32(float x) {
    uint32_t r;
    asm("cvt.rna.tf32.f32 %0, %1;" : "=r"(r) : "f"(x));
    return r;
}
__device__ __forceinline__ float tf32v(float x) {
    return __uint_as_float(f32_to_tf32(x));
}
__device__ __forceinline__ void mma_tf32(float c[4], const uint32_t a[4], const uint32_t b[2]) {
    asm volatile(
        "mma.sync.aligned.m16n8k8.row.col.f32.tf32.tf32.f32 "
        "{%0,%1,%2,%3}, {%4,%5,%6,%7}, {%8,%9}, {%0,%1,%2,%3};\n"
        : "+f"(c[0]), "+f"(c[1]), "+f"(c[2]), "+f"(c[3])
        : "r"(a[0]), "r"(a[1]), "r"(a[2]), "r"(a[3]), "r"(b[0]), "r"(b[1]));
}
__device__ __forceinline__ uint32_t smem_u32(const void* p) {
    uint32_t a;
    asm("{ .reg .u64 t; cvta.to.shared.u64 t, %1; cvt.u32.u64 %0, t; }" : "=r"(a) : "l"(p));
    return a;
}
__device__ __forceinline__ void cp_async16(uint32_t dst, const void* src) {
    asm volatile("cp.async.ca.shared.global [%0], [%1], 16;\n" :: "r"(dst), "l"(src));
}
__device__ __forceinline__ void cp_async16_p(uint32_t dst, const void* src, bool pred) {
    int sz = pred ? 16 : 0;
    asm volatile("cp.async.ca.shared.global [%0], [%1], 16, %2;\n"
                 :: "r"(dst), "l"(src), "r"(sz));
}
__device__ __forceinline__ void cp_commit() {
    asm volatile("cp.async.commit_group;\n");
}
__device__ __forceinline__ void cp_wait1() {
    asm volatile("cp.async.wait_group 1;\n" ::: "memory");
}
__device__ __forceinline__ void cp_wait0() {
    asm volatile("cp.async.wait_group 0;\n" ::: "memory");
}

// ================= prep: W1 [j][k] -> W1tp [k][j] (tf32, 264-stride) ========
__global__ void k_prepW1(const float* __restrict__ W1) {
    __shared__ float tile[32][33];
    int k0 = blockIdx.x * 32, j0 = blockIdx.y * 32;
    int tx = threadIdx.x, ty = threadIdx.y;  // 32 x 8
#pragma unroll
    for (int r = 0; r < 32; r += 8)
        tile[ty + r][tx] = W1[(j0 + ty + r) * U + k0 + tx];
    __syncthreads();
#pragma unroll
    for (int r = 0; r < 32; r += 8)
        g_W1tp[(size_t)(k0 + ty + r) * 264 + j0 + tx] = tf32v(tile[tx][ty + r]);
}

// ================= K2: scores via pipelined tf32 mma (unchanged) ============
__global__ void __launch_bounds__(256, 1)
k_scores3(const float* __restrict__ memory, const float* __restrict__ v) {
    extern __shared__ float dsm[];
    float* Abuf = dsm;                         // 2 * 4608 floats
    float* Bbuf = dsm + 2 * 128 * 36;          // 2 * 8448 floats
    __shared__ float sq[U], sv[U];
    __shared__ float spart[128][4];

    int b = blockIdx.x, t0 = blockIdx.y * 128;
    int tid = threadIdx.x, lane = tid & 31, w = tid >> 5;

    sq[tid] = g_query[b * U + tid];
    sv[tid] = v[tid];

    const float* Abase = memory + ((size_t)b * TLEN + t0) * U;

    int mbase = (w & 1) * 64;
    int nbase = (w >> 1) * 64;
    int r0 = lane >> 2, cA = lane & 3;
    int rB = lane & 3, cB = lane >> 2;

    float acc[4][8][4];
#pragma unroll
    for (int mt = 0; mt < 4; mt++)
#pragma unroll
        for (int nt = 0; nt < 8; nt++)
#pragma unroll
            for (int i = 0; i < 4; i++) acc[mt][nt][i] = 0.0f;

#pragma unroll
    for (int i = 0; i < 4; i++) {
        int u = tid + 256 * i;
        int row = u >> 3, c4 = (u & 7) * 4;
        cp_async16(smem_u32(Abuf + row * 36 + c4), Abase + (size_t)row * U + c4);
    }
#pragma unroll
    for (int i = 0; i < 8; i++) {
        int u = tid + 256 * i;
        int row = u >> 6, c4 = (u & 63) * 4;
        cp_async16(smem_u32(Bbuf + row * 264 + c4), g_W1tp + (size_t)row * 264 + c4);
    }
    cp_commit();

    for (int kc = 0; kc < 8; kc++) {
        int buf = kc & 1;
        if (kc < 7) {
            float* An = Abuf + (buf ^ 1) * 4608;
            float* Bn = Bbuf + (buf ^ 1) * 8448;
#pragma unroll
            for (int i = 0; i < 4; i++) {
                int u = tid + 256 * i;
                int row = u >> 3, c4 = (u & 7) * 4;
                cp_async16(smem_u32(An + row * 36 + c4),
                           Abase + (size_t)row * U + (kc + 1) * 32 + c4);
            }
#pragma unroll
            for (int i = 0; i < 8; i++) {
                int u = tid + 256 * i;
                int row = u >> 6, c4 = (u & 63) * 4;
                cp_async16(smem_u32(Bn + row * 264 + c4),
                           g_W1tp + (size_t)((kc + 1) * 32 + row) * 264 + c4);
            }
            cp_commit();
            cp_wait1();
        } else {
            cp_wait0();
        }
        __syncthreads();

        const float* Ac = Abuf + buf * 4608;
        const float* Bc = Bbuf + buf * 8448;
#pragma unroll
        for (int kk = 0; kk < 32; kk += 8) {
            uint32_t a[4][4];
#pragma unroll
            for (int mt = 0; mt < 4; mt++) {
                a[mt][0] = f32_to_tf32(Ac[(mbase + mt * 16 + r0) * 36 + kk + cA]);
                a[mt][1] = f32_to_tf32(Ac[(mbase + mt * 16 + r0 + 8) * 36 + kk + cA]);
                a[mt][2] = f32_to_tf32(Ac[(mbase + mt * 16 + r0) * 36 + kk + cA + 4]);
                a[mt][3] = f32_to_tf32(Ac[(mbase + mt * 16 + r0 + 8) * 36 + kk + cA + 4]);
            }
            uint32_t bb[8][2];
#pragma unroll
            for (int nt = 0; nt < 8; nt++) {
                int j = nbase + nt * 8 + cB;
                bb[nt][0] = __float_as_uint(Bc[(kk + rB) * 264 + j]);
                bb[nt][1] = __float_as_uint(Bc[(kk + rB + 4) * 264 + j]);
            }
#pragma unroll
            for (int mt = 0; mt < 4; mt++)
#pragma unroll
                for (int nt = 0; nt < 8; nt++)
                    mma_tf32(acc[mt][nt], a[mt], bb[nt]);
        }
        __syncthreads();
    }

    float part[8];
#pragma unroll
    for (int i = 0; i < 8; i++) part[i] = 0.0f;
    int q4 = lane & 3;
#pragma unroll
    for (int mt = 0; mt < 4; mt++) {
#pragma unroll
        for (int nt = 0; nt < 8; nt++) {
            int j0 = nbase + nt * 8 + 2 * q4;
            float q0 = sq[j0], q1 = sq[j0 + 1];
            float v0 = sv[j0], v1 = sv[j0 + 1];
            part[mt * 2 + 0] += v0 * tanh_fast(acc[mt][nt][0] + q0) + v1 * tanh_fast(acc[mt][nt][1] + q1);
            part[mt * 2 + 1] += v0 * tanh_fast(acc[mt][nt][2] + q0) + v1 * tanh_fast(acc[mt][nt][3] + q1);
        }
    }
#pragma unroll
    for (int i = 0; i < 8; i++) {
        part[i] += __shfl_xor_sync(0xffffffffu, part[i], 1);
        part[i] += __shfl_xor_sync(0xffffffffu, part[i], 2);
    }
    if ((lane & 3) == 0) {
#pragma unroll
        for (int mt = 0; mt < 4; mt++) {
            spart[mbase + mt * 16 + r0][w >> 1] = part[mt * 2 + 0];
            spart[mbase + mt * 16 + r0 + 8][w >> 1] = part[mt * 2 + 1];
        }
    }
    __syncthreads();
    if (tid < 128) {
        float s = spart[tid][0] + spart[tid][1] + spart[tid][2] + spart[tid][3];
        g_scores[b * TLEN + t0 + tid] = s;
    }
}

// ================= Pipelined generic GEMM: C[128 x N] = A @ W^T + bias ======
#define GAF 4608   // 128*36 floats per A buffer
#define GWF 2304   // 64*36 floats per W buffer
__device__ __forceinline__ void gemm_pipe(const float* __restrict__ A, int lda,
                                          const float* __restrict__ W,
                                          const float* __restrict__ bias,
                                          float* __restrict__ C, int ldc,
                                          int N, int K, int n0, float* dsm) {
    float* Ab = dsm;
    float* Wb = dsm + 2 * GAF;
    int tid = threadIdx.x, lane = tid & 31, w = tid >> 5;
    int nch = K >> 5;

    float acc[2][4][4];
#pragma unroll
    for (int mt = 0; mt < 2; mt++)
#pragma unroll
        for (int nt = 0; nt < 4; nt++)
#pragma unroll
            for (int i = 0; i < 4; i++) acc[mt][nt][i] = 0.0f;

    int mbase = (w & 3) * 32;
    int nbase = (w >> 2) * 32;
    int r0 = lane >> 2, cA = lane & 3;
    int rW = lane >> 2, cW = lane & 3;

    // prologue: A 128x32 (1024 f4), W 64x32 (512 f4)
#pragma unroll
    for (int i = 0; i < 4; i++) {
        int u = tid + 256 * i;
        int row = u >> 3, c4 = (u & 7) * 4;
        cp_async16(smem_u32(Ab + row * 36 + c4), A + (size_t)row * lda + c4);
    }
#pragma unroll
    for (int i = 0; i < 2; i++) {
        int u = tid + 256 * i;
        int row = u >> 3, c4 = (u & 7) * 4;
        int n = n0 + row;
        int nc = n < N ? n : N - 1;
        cp_async16_p(smem_u32(Wb + row * 36 + c4), W + (size_t)nc * K + c4, n < N);
    }
    cp_commit();

    for (int kc = 0; kc < nch; kc++) {
        int buf = kc & 1;
        if (kc + 1 < nch) {
            float* An = Ab + (buf ^ 1) * GAF;
            float* Wn = Wb + (buf ^ 1) * GWF;
            int k0 = (kc + 1) * 32;
#pragma unroll
            for (int i = 0; i < 4; i++) {
                int u = tid + 256 * i;
                int row = u >> 3, c4 = (u & 7) * 4;
                cp_async16(smem_u32(An + row * 36 + c4), A + (size_t)row * lda + k0 + c4);
            }
#pragma unroll
            for (int i = 0; i < 2; i++) {
                int u = tid + 256 * i;
                int row = u >> 3, c4 = (u & 7) * 4;
                int n = n0 + row;
                int nc = n < N ? n : N - 1;
                cp_async16_p(smem_u32(Wn + row * 36 + c4), W + (size_t)nc * K + k0 + c4, n < N);
            }
            cp_commit();
            cp_wait1();
        } else {
            cp_wait0();
        }
        __syncthreads();

        const float* Ac = Ab + buf * GAF;
        const float* Wc = Wb + buf * GWF;
#pragma unroll
        for (int kk = 0; kk < 32; kk += 8) {
            uint32_t a[2][4];
#pragma unroll
            for (int mt = 0; mt < 2; mt++) {
                a[mt][0] = f32_to_tf32(Ac[(mbase + mt * 16 + r0) * 36 + kk + cA]);
                a[mt][1] = f32_to_tf32(Ac[(mbase + mt * 16 + r0 + 8) * 36 + kk + cA]);
                a[mt][2] = f32_to_tf32(Ac[(mbase + mt * 16 + r0) * 36 + kk + cA + 4]);
                a[mt][3] = f32_to_tf32(Ac[(mbase + mt * 16 + r0 + 8) * 36 + kk + cA + 4]);
            }
            uint32_t bb[4][2];
#pragma unroll
            for (int nt = 0; nt < 4; nt++) {
                int nl = nbase + nt * 8 + rW;
                bb[nt][0] = f32_to_tf32(Wc[nl * 36 + kk + cW]);
                bb[nt][1] = f32_to_tf32(Wc[nl * 36 + kk + cW + 4]);
            }
#pragma unroll
            for (int mt = 0; mt < 2; mt++)
#pragma unroll
                for (int nt = 0; nt < 4; nt++)
                    mma_tf32(acc[mt][nt], a[mt], bb[nt]);
        }
        __syncthreads();
    }

    int q4 = lane & 3;
#pragma unroll
    for (int mt = 0; mt < 2; mt++) {
#pragma unroll
        for (int nt = 0; nt < 4; nt++) {
            int m = mbase + mt * 16 + r0;
            int n = n0 + nbase + nt * 8 + 2 * q4;
            if (n < N) {
                float b0 = bias ? bias[n] : 0.0f;
                float b1 = bias ? bias[n + 1] : 0.0f;
                C[(size_t)m * ldc + n]           = acc[mt][nt][0] + b0;
                C[(size_t)m * ldc + n + 1]       = acc[mt][nt][1] + b1;
                C[(size_t)(m + 8) * ldc + n]     = acc[mt][nt][2] + b0;
                C[(size_t)(m + 8) * ldc + n + 1] = acc[mt][nt][3] + b1;
            }
        }
    }
}

__global__ void __launch_bounds__(256)
k_gemm_p(const float* __restrict__ A, int lda, const float* __restrict__ W,
         const float* __restrict__ bias, float* __restrict__ C, int ldc,
         int N, int K) {
    extern __shared__ float dsm[];
    gemm_pipe(A, lda, W, bias, C, ldc, N, K, blockIdx.x * 64, dsm);
}

struct GemmJob {
    const float* A; const float* W; const float* bias; float* C;
    int lda; int ldc; int N; int K;
};
struct GemmJobs3 { GemmJob j[3]; };

__global__ void __launch_bounds__(256)
k_gemm_multi_p(GemmJobs3 jobs) {
    extern __shared__ float dsm[];
    GemmJob jb = jobs.j[blockIdx.y];
    gemm_pipe(jb.A, jb.lda, jb.W, jb.bias, jb.C, jb.ldc, jb.N, jb.K,
              blockIdx.x * 64, dsm);
}

// ================= Fused gate-GEMM + GRU combine =================
// Block computes gates r/z/n for j in [n0,n0+64), m in [m0,m0+32), then
// applies the GRU cell with precomputed hidden-side pre-acts.
#define GRA 1152   // 32*36
#define GRW 6912   // 192*36
__global__ void __launch_bounds__(256)
k_gemm_gru(const float* __restrict__ A, int lda, int K,
           const float* __restrict__ Wih, const float* __restrict__ bih,
           const float* __restrict__ gh, const float* __restrict__ h0,
           float* __restrict__ hA, int sHA, float* __restrict__ hB,
           float* __restrict__ xout) {
    extern __shared__ float dsm[];
    float* Ab = dsm;                  // 2 * GRA
    float* Wb = dsm + 2 * GRA;        // 2 * GRW
    int tid = threadIdx.x, lane = tid & 31, w = tid >> 5;
    int n0 = blockIdx.x * 64;
    int m0 = blockIdx.y * 32;
    int nch = K >> 5;
    int mbase = (w & 1) * 16, nbase = (w >> 1) * 16;
    int r0 = lane >> 2, cA = lane & 3;
    int rW = lane >> 2, cW = lane & 3;

    float acc[3][2][4];
#pragma unroll
    for (int g = 0; g < 3; g++)
#pragma unroll
        for (int nt = 0; nt < 2; nt++)
#pragma unroll
            for (int i = 0; i < 4; i++) acc[g][nt][i] = 0.0f;

    // prologue: A 32x32 (256 f4, 1 iter), W 192x32 (1536 f4, 6 iters)
    {
        int row = tid >> 3, c4 = (tid & 7) * 4;
        cp_async16(smem_u32(Ab + row * 36 + c4), A + (size_t)(m0 + row) * lda + c4);
    }
#pragma unroll
    for (int i = 0; i < 6; i++) {
        int u = tid + 256 * i;
        int row = u >> 3, c4 = (u & 7) * 4;
        int wr = (row >> 6) * 256 + n0 + (row & 63);
        cp_async16(smem_u32(Wb + row * 36 + c4), Wih + (size_t)wr * K + c4);
    }
    cp_commit();

    for (int kc = 0; kc < nch; kc++) {
        int buf = kc & 1;
        if (kc + 1 < nch) {
            float* An = Ab + (buf ^ 1) * GRA;
            float* Wn = Wb + (buf ^ 1) * GRW;
            int k0 = (kc + 1) * 32;
            {
                int row = tid >> 3, c4 = (tid & 7) * 4;
                cp_async16(smem_u32(An + row * 36 + c4),
                           A + (size_t)(m0 + row) * lda + k0 + c4);
            }
#pragma unroll
            for (int i = 0; i < 6; i++) {
                int u = tid + 256 * i;
                int row = u >> 3, c4 = (u & 7) * 4;
                int wr = (row >> 6) * 256 + n0 + (row & 63);
                cp_async16(smem_u32(Wn + row * 36 + c4), Wih + (size_t)wr * K + k0 + c4);
            }
            cp_commit();
            cp_wait1();
        } else {
            cp_wait0();
        }
        __syncthreads();

        const float* Ac = Ab + buf * GRA;
        const float* Wc = Wb + buf * GRW;
#pragma unroll
        for (int kk = 0; kk < 32; kk += 8) {
            uint32_t a[4];
            a[0] = f32_to_tf32(Ac[(mbase + r0) * 36 + kk + cA]);
            a[1] = f32_to_tf32(Ac[(mbase + r0 + 8) * 36 + kk + cA]);
            a[2] = f32_to_tf32(Ac[(mbase + r0) * 36 + kk + cA + 4]);
            a[3] = f32_to_tf32(Ac[(mbase + r0 + 8) * 36 + kk + cA + 4]);
#pragma unroll
            for (int g = 0; g < 3; g++) {
#pragma unroll
                for (int nt = 0; nt < 2; nt++) {
                    uint32_t bb[2];
                    int nl = g * 64 + nbase + nt * 8 + rW;
                    bb[0] = f32_to_tf32(Wc[nl * 36 + kk + cW]);
                    bb[1] = f32_to_tf32(Wc[nl * 36 + kk + cW + 4]);
                    mma_tf32(acc[g][nt], a, bb);
                }
            }
        }
        __syncthreads();
    }

    // epilogue: GRU combine
    int q4 = lane & 3;
#pragma unroll
    for (int nt = 0; nt < 2; nt++) {
#pragma unroll
        for (int half = 0; half < 2; half++) {
            int m = m0 + mbase + r0 + half * 8;
#pragma unroll
            for (int c = 0; c < 2; c++) {
                int nn = n0 + nbase + nt * 8 + 2 * q4 + c;
                int ai = half * 2 + c;
                float gir = acc[0][nt][ai] + bih[nn];
                float giz = acc[1][nt][ai] + bih[256 + nn];
                float gin = acc[2][nt][ai] + bih[512 + nn];
                float ghr = gh[m * 768 + nn];
                float ghz = gh[m * 768 + 256 + nn];
                float ghn = gh[m * 768 + 512 + nn];
                float r = sigmoidf_(gir + ghr);
                float z = sigmoidf_(giz + ghz);
                float nv = tanhf(gin + r * ghn);
                float h = (1.0f - z) * nv + z * h0[m * 256 + nn];
                hA[(size_t)m * sHA + nn] = h;
                if (hB) hB[m * 256 + nn] = h;
                if (xout) xout[m * 256 + nn] = A[(size_t)m * lda + nn] + h;
            }
        }
    }
}

// ================= softmax stats; normalize in place =================
__global__ void k_softmax_stats() {
    int b = blockIdx.x;
    int tid = threadIdx.x;
    int lane = tid & 31, warp = tid >> 5;
    __shared__ float red[8];

    float4 s = *(const float4*)(g_scores + b * TLEN + tid * 4);
    float m = fmaxf(fmaxf(s.x, s.y), fmaxf(s.z, s.w));
#pragma unroll
    for (int off = 16; off; off >>= 1) m = fmaxf(m, __shfl_xor_sync(0xffffffffu, m, off));
    if (lane == 0) red[warp] = m;
    __syncthreads();
    if (tid == 0) {
        float mm = red[0];
#pragma unroll
        for (int i = 1; i < 8; i++) mm = fmaxf(mm, red[i]);
        red[0] = mm;
    }
    __syncthreads();
    float mx = red[0];
    __syncthreads();

    float4 e;
    e.x = __expf(s.x - mx); e.y = __expf(s.y - mx);
    e.z = __expf(s.z - mx); e.w = __expf(s.w - mx);
    float t = e.x + e.y + e.z + e.w;
#pragma unroll
    for (int off = 16; off; off >>= 1) t += __shfl_xor_sync(0xffffffffu, t, off);
    if (lane == 0) red[warp] = t;
    __syncthreads();
    if (tid == 0) {
        float ss = 0.0f;
#pragma unroll
        for (int i = 0; i < 8; i++) ss += red[i];
        red[0] = 1.0f / ss;
    }
    __syncthreads();
    float inv = red[0];
    e.x *= inv; e.y *= inv; e.z *= inv; e.w *= inv;
    *(float4*)(g_scores + b * TLEN + tid * 4) = e;
}

// ================= context partials (grid B x 4) =================
__global__ void __launch_bounds__(256, 4)
k_context(const float* __restrict__ memory) {
    int b = blockIdx.x, ch = blockIdx.y;
    int tid = threadIdx.x;
    int u4 = tid & 63;
    int tg = tid >> 6;

    __shared__ float sw[256];
    __shared__ float4 part[4][64];

    sw[tid] = g_scores[b * TLEN + ch * 256 + tid];
    __syncthreads();

    const float* mp = memory + ((size_t)b * TLEN + ch * 256 + tg * 64) * U + u4 * 4;
    const float* wp = sw + tg * 64;
    float4 c = make_float4(0.f, 0.f, 0.f, 0.f);
#pragma unroll 8
    for (int i = 0; i < 64; i++) {
        float wv = wp[i];
        float4 m4 = *(const float4*)(mp + (size_t)i * U);
        c.x += wv * m4.x; c.y += wv * m4.y; c.z += wv * m4.z; c.w += wv * m4.w;
    }
    part[tg][u4] = c;
    __syncthreads();

    if (tg == 0) {
        float4 a = part[0][u4], b2 = part[1][u4], c2 = part[2][u4], d2 = part[3][u4];
        float4 r;
        r.x = a.x + b2.x + c2.x + d2.x;
        r.y = a.y + b2.y + c2.y + d2.y;
        r.z = a.z + b2.z + c2.z + d2.z;
        r.w = a.w + b2.w + c2.w + d2.w;
        *(float4*)(g_ctxpart + ((size_t)b * 4 + ch) * U + u4 * 4) = r;
    }
}

__global__ void k_ctx_reduce() {
    int b = blockIdx.x, j = threadIdx.x;
    g_cat[b * 2 * U + U + j] = g_ctxpart[((size_t)b * 4 + 0) * U + j]
                             + g_ctxpart[((size_t)b * 4 + 1) * U + j]
                             + g_ctxpart[((size_t)b * 4 + 2) * U + j]
                             + g_ctxpart[((size_t)b * 4 + 3) * U + j];
}

// ================= launch =================
extern "C" void kernel_launch(void* const* d_in, const int* in_sizes, int n_in,
                              void* d_out, int out_size) {
    const float* dec   = (const float*)d_in[0];
    const float* mem   = (const float*)d_in[1];
    const float* ah    = (const float*)d_in[2];
    const float* h1    = (const float*)d_in[3];
    const float* h2    = (const float*)d_in[4];
    const float* W1    = (const float*)d_in[5];
    const float* W2    = (const float*)d_in[6];
    const float* v     = (const float*)d_in[7];
    const float* aWih  = (const float*)d_in[8];
    const float* aWhh  = (const float*)d_in[9];
    const float* abih  = (const float*)d_in[10];
    const float* abhh  = (const float*)d_in[11];
    const float* g1Wih = (const float*)d_in[12];
    const float* g1Whh = (const float*)d_in[13];
    const float* g1bih = (const float*)d_in[14];
    const float* g1bhh = (const float*)d_in[15];
    const float* g2Wih = (const float*)d_in[16];
    const float* g2Whh = (const float*)d_in[17];
    const float* g2bih = (const float*)d_in[18];
    const float* g2bhh = (const float*)d_in[19];
    const float* projW = (const float*)d_in[20];
    const float* projb = (const float*)d_in[21];
    const float* outW  = (const float*)d_in[22];
    const float* outb  = (const float*)d_in[23];
    float* out = (float*)d_out;

    float* p_ghA;   cudaGetSymbolAddress((void**)&p_ghA, g_ghA);
    float* p_gh1;   cudaGetSymbolAddress((void**)&p_gh1, g_gh1);
    float* p_gh2;   cudaGetSymbolAddress((void**)&p_gh2, g_gh2);
    float* p_cat;   cudaGetSymbolAddress((void**)&p_cat, g_cat);
    float* p_x1;    cudaGetSymbolAddress((void**)&p_x1, g_x1);
    float* p_x2;    cudaGetSymbolAddress((void**)&p_x2, g_x2);
    float* p_bf;    cudaGetSymbolAddress((void**)&p_bf, g_bf);
    float* p_query; cudaGetSymbolAddress((void**)&p_query, g_query);

    static int smem_set = 0;
    const int SC_SMEM = (2 * 128 * 36 + 2 * 32 * 264) * 4;   // 104448 B
    const int GP_SMEM = 2 * (GAF + GWF) * 4;                 // 55296 B
    const int GR_SMEM = 2 * (GRA + GRW) * 4;                 // 64512 B
    if (!smem_set) {
        cudaFuncSetAttribute(k_scores3, cudaFuncAttributeMaxDynamicSharedMemorySize, SC_SMEM);
        cudaFuncSetAttribute(k_gemm_p, cudaFuncAttributeMaxDynamicSharedMemorySize, GP_SMEM);
        cudaFuncSetAttribute(k_gemm_multi_p, cudaFuncAttributeMaxDynamicSharedMemorySize, GP_SMEM);
        cudaFuncSetAttribute(k_gemm_gru, cudaFuncAttributeMaxDynamicSharedMemorySize, GR_SMEM);
        smem_set = 1;
    }

    k_prepW1<<<dim3(8, 8), dim3(32, 8)>>>(W1);

    // hidden-side gate pre-acts (input-independent): one multi launch
    GemmJobs3 jobs;
    jobs.j[0] = { ah, aWhh,  abhh,  p_ghA, U, 768, 768, U };
    jobs.j[1] = { h1, g1Whh, g1bhh, p_gh1, U, 768, 768, U };
    jobs.j[2] = { h2, g2Whh, g2bhh, p_gh2, U, 768, 768, U };
    k_gemm_multi_p<<<dim3(12, 3), 256, GP_SMEM>>>(jobs);

    // attention GRU: fused gate-GEMM + combine -> d_t (g_cat cols [0,256) + d_out)
    k_gemm_gru<<<dim3(4, 4), 256, GR_SMEM>>>(dec, INWID, INWID, aWih, abih,
                                             p_ghA, ah, p_cat, 2 * U,
                                             out + DT_OFF, nullptr);

    // query = d_t @ W2^T
    k_gemm_p<<<4, 256, GP_SMEM>>>(p_cat, 2 * U, W2, nullptr, p_query, U, U, U);

    k_scores3<<<dim3(BATCH, TLEN / 128), 256, SC_SMEM>>>(mem, v);
    k_softmax_stats<<<BATCH, 256>>>();
    k_context<<<dim3(BATCH, 4), 256>>>(mem);
    k_ctx_reduce<<<BATCH, 256>>>();

    // gru1_input = [d_t | ctx] @ projW^T + projb
    k_gemm_p<<<4, 256, GP_SMEM>>>(p_cat, 2 * U, projW, projb, p_x1, U, U, 2 * U);

    // GRU1: fused gate-GEMM + combine -> h1 (d_out) and x2 = x1 + h1
    k_gemm_gru<<<dim3(4, 4), 256, GR_SMEM>>>(p_x1, U, U, g1Wih, g1bih,
                                             p_gh1, h1, out + G1_OFF, U,
                                             nullptr, p_x2);

    // GRU2: fused gate-GEMM + combine -> h2 (d_out) and bf = x2 + h2
    k_gemm_gru<<<dim3(4, 4), 256, GR_SMEM>>>(p_x2, U, U, g2Wih, g2bih,
                                             p_gh2, h2, out + G2_OFF, U,
                                             nullptr, p_bf);

    // output head
    k_gemm_p<<<7, 256, GP_SMEM>>>(p_bf, U, outW, outb, out + OUT_OFF, OUTD, OUTD, U);
}